// round 5
// baseline (speedup 1.0000x reference)
#include <cuda_runtime.h>
#include <cstdint>

// Shape-fixed problem: N=20000, K=32, C=512, OUT=512
#define C_DIM   512
#define OUT_DIM 512
#define K_NB    32

#define BM      64            // rows per block-tile
#define BN      256           // cols per bx pass (2 passes = 512)
#define AGSTR   516           // agg smem row stride (words): (4r+fc) mod 32 distinct
#define SSTR    36            // stage row stride (words)
#define NSTAGE  2
#define THREADS 256
#define NCH     32            // chunks per bx pass: 0-15 agg/Wr, 16-31 x/Wl

#define A_WORDS   (BM * SSTR)                  // 2304
#define B_WORDS   (BN * SSTR)                  // 9216
#define STG_WORDS (A_WORDS + B_WORDS)          // 11520
#define AGG_WORDS (BM * AGSTR)                 // 33024
#define BAR_WOFF  (AGG_WORDS + NSTAGE * STG_WORDS)   // 56064 words
#define SMEM_BYTES ((BAR_WOFF + 64) * 4)       // 224512 bytes

// tf32-bit weights (pre-converted once)
__device__ uint32_t g_wl[OUT_DIM * C_DIM];
__device__ uint32_t g_wr[OUT_DIM * C_DIM];

__device__ __forceinline__ uint32_t f2tf32(float f) {
    uint32_t r;
    asm("cvt.rna.tf32.f32 %0, %1;" : "=r"(r) : "f"(f));
    return r;
}

__device__ __forceinline__ void mma_tf32(float* c, const uint32_t* a, const uint32_t* b) {
    asm volatile(
        "mma.sync.aligned.m16n8k8.row.col.f32.tf32.tf32.f32 "
        "{%0,%1,%2,%3}, {%4,%5,%6,%7}, {%8,%9}, {%0,%1,%2,%3};"
        : "+f"(c[0]), "+f"(c[1]), "+f"(c[2]), "+f"(c[3])
        : "r"(a[0]), "r"(a[1]), "r"(a[2]), "r"(a[3]), "r"(b[0]), "r"(b[1]));
}

__device__ __forceinline__ void cp_async16(uint32_t saddr, const void* gsrc, int src_bytes) {
    asm volatile("cp.async.cg.shared.global [%0], [%1], 16, %2;\n"
                 :: "r"(saddr), "l"(gsrc), "r"(src_bytes));
}

#define MBAR_INIT(addr, cnt) \
    asm volatile("mbarrier.init.shared.b64 [%0], %1;" :: "r"(addr), "r"((uint32_t)(cnt)) : "memory")

#define MBAR_ARRIVE(addr) \
    asm volatile("mbarrier.arrive.shared.b64 _, [%0];" :: "r"(addr) : "memory")

#define MBAR_WAIT(addr, par) do { \
    uint32_t _m = (addr); uint32_t _p = (uint32_t)(par); uint32_t _done; \
    asm volatile("{\n\t.reg .pred p;\n\t" \
        "mbarrier.try_wait.parity.acquire.cta.shared::cta.b64 p, [%1], %2;\n\t" \
        "selp.b32 %0, 1, 0, p;\n\t}" : "=r"(_done) : "r"(_m), "r"(_p) : "memory"); \
    if (!_done) { \
        asm volatile("{\n\t.reg .pred P1;\n\t" \
            "WL_%=:\n\t" \
            "mbarrier.try_wait.parity.acquire.cta.shared::cta.b64 P1, [%0], %1, 0x989680;\n\t" \
            "@P1 bra.uni WD_%=;\n\t" \
            "bra.uni WL_%=;\n\t" \
            "WD_%=:\n\t}" :: "r"(_m), "r"(_p) : "memory"); \
    } } while (0)

// ---------------------------------------------------------------------------
// Micro-kernel: convert W_l, W_r fp32 -> tf32 bits (1 float4 per thread)
// ---------------------------------------------------------------------------
__global__ void __launch_bounds__(256) wconv_kernel(const float* __restrict__ wl,
                                                    const float* __restrict__ wr)
{
    int i = blockIdx.x * 256 + threadIdx.x;        // 0..131071
    const bool isL = (i < 65536);
    int j = isL ? i : i - 65536;
    float4 v = reinterpret_cast<const float4*>(isL ? wl : wr)[j];
    uint4 o;
    o.x = f2tf32(v.x); o.y = f2tf32(v.y); o.z = f2tf32(v.z); o.w = f2tf32(v.w);
    reinterpret_cast<uint4*>(isL ? g_wl : g_wr)[j] = o;
}

// ---------------------------------------------------------------------------
// Fused persistent kernel.
// Warps 0-3: consumers (tf32 mma.sync, 64x256 tile per bx, acc in regs)
// Warps 4-7: producers (neigh_x mean -> agg smem; cp.async stage fills)
// Chunk order per bx pass: c=0..15 agg (A from agg smem, B=Wr),
//                          c=16..31 x  (A from stage fp32 + cvt, B=Wl)
// ---------------------------------------------------------------------------
__global__ void __launch_bounds__(THREADS, 1)
fused_kernel(const float* __restrict__ x,
             const float* __restrict__ nx,
             const float* __restrict__ bl,
             const float* __restrict__ br,
             float* __restrict__ out,
             int Nrows, int NBLK)
{
    extern __shared__ uint32_t smw[];
    uint32_t* aggw = smw;                                   // AGG_WORDS
    const uint32_t smem_u32 = (uint32_t)__cvta_generic_to_shared(smw);
    const uint32_t stg_base = smem_u32 + AGG_WORDS * 4;
    const uint32_t bar_base = smem_u32 + BAR_WOFF * 4;
    // bars: full[s]=bar_base+s*8, empty[s]=+16+s*8, ready[c]=+32+c*8

    const int tid  = threadIdx.x;
    const int lane = tid & 31;
    const int wid  = tid >> 5;

    if (tid == 0) {
        MBAR_INIT(bar_base + 0, 128);  MBAR_INIT(bar_base + 8, 128);      // full
        MBAR_INIT(bar_base + 16, 128); MBAR_INIT(bar_base + 24, 128);     // empty
        for (int c = 0; c < 16; ++c) MBAR_INIT(bar_base + 32 + c * 8, 128); // ready
    }
    __syncthreads();

    int fidx = 0;     // global stage-fill counter (lockstep producer/consumer)
    int it   = 0;     // row-block ordinal (ready-bar parity)

    for (int blk = blockIdx.x; blk < NBLK; blk += gridDim.x, ++it) {
        const int rowBase = blk * BM;

        if (wid >= 4) {
            // ================= PRODUCERS =================
            const int ptid = tid - 128;          // 0..127
            const int prow = ptid >> 1;          // 0..63
            const int half = ptid & 1;           // 16-col half

            for (int bx = 0; bx < 2; ++bx) {
                for (int c = 0; c < NCH; ++c) {
                    // --- agg chunk compute (bx==0 only) ---
                    if (bx == 0 && c < 16) {
                        const int kk = c * 32;
                        float4 s0 = {0,0,0,0}, s1 = {0,0,0,0}, s2 = {0,0,0,0}, s3 = {0,0,0,0};
                        const int grow = rowBase + prow;
                        if (grow < Nrows) {
                            const float4* p = reinterpret_cast<const float4*>(nx)
                                            + (size_t)grow * (K_NB * C_DIM / 4)
                                            + (kk >> 2) + half * 4;
#pragma unroll 8
                            for (int nb = 0; nb < K_NB; ++nb) {
                                float4 v0 = p[(size_t)nb * (C_DIM / 4) + 0];
                                float4 v1 = p[(size_t)nb * (C_DIM / 4) + 1];
                                float4 v2 = p[(size_t)nb * (C_DIM / 4) + 2];
                                float4 v3 = p[(size_t)nb * (C_DIM / 4) + 3];
                                s0.x += v0.x; s0.y += v0.y; s0.z += v0.z; s0.w += v0.w;
                                s1.x += v1.x; s1.y += v1.y; s1.z += v1.z; s1.w += v1.w;
                                s2.x += v2.x; s2.y += v2.y; s2.z += v2.z; s2.w += v2.w;
                                s3.x += v3.x; s3.y += v3.y; s3.z += v3.z; s3.w += v3.w;
                            }
                        }
                        const float inv = 1.0f / (float)K_NB;
                        uint32_t* d = aggw + prow * AGSTR + kk + half * 16;
                        uint4 o;
                        o.x = f2tf32(s0.x * inv); o.y = f2tf32(s0.y * inv);
                        o.z = f2tf32(s0.z * inv); o.w = f2tf32(s0.w * inv);
                        reinterpret_cast<uint4*>(d)[0] = o;
                        o.x = f2tf32(s1.x * inv); o.y = f2tf32(s1.y * inv);
                        o.z = f2tf32(s1.z * inv); o.w = f2tf32(s1.w * inv);
                        reinterpret_cast<uint4*>(d)[1] = o;
                        o.x = f2tf32(s2.x * inv); o.y = f2tf32(s2.y * inv);
                        o.z = f2tf32(s2.z * inv); o.w = f2tf32(s2.w * inv);
                        reinterpret_cast<uint4*>(d)[2] = o;
                        o.x = f2tf32(s3.x * inv); o.y = f2tf32(s3.y * inv);
                        o.z = f2tf32(s3.z * inv); o.w = f2tf32(s3.w * inv);
                        reinterpret_cast<uint4*>(d)[3] = o;
                        MBAR_ARRIVE(bar_base + 32 + c * 8);
                    }
                    // --- stage fill ---
                    const int b = fidx & 1;
                    if (fidx >= 2) MBAR_WAIT(bar_base + 16 + b * 8, ((fidx >> 1) - 1) & 1);
                    const uint32_t sA = stg_base + b * STG_WORDS * 4;
                    const uint32_t sB = sA + A_WORDS * 4;
                    if (c >= 16) {                      // x chunk: A tile (fp32)
                        const int kk = (c - 16) * 32;
#pragma unroll
                        for (int i = 0; i < 4; ++i) {
                            int idx = i * 128 + ptid;   // 0..511
                            int r = idx >> 3, c4 = (idx & 7) * 4;
                            int grow = rowBase + r;
                            cp_async16(sA + (r * SSTR + c4) * 4,
                                       x + (size_t)grow * C_DIM + kk + c4,
                                       (grow < Nrows) ? 16 : 0);
                        }
                    }
                    {
                        const uint32_t* Bp = (c < 16) ? g_wr : g_wl;
                        const int kk = (c < 16) ? c * 32 : (c - 16) * 32;
#pragma unroll
                        for (int i = 0; i < 16; ++i) {
                            int idx = i * 128 + ptid;   // 0..2047
                            int o = idx >> 3, c4 = (idx & 7) * 4;
                            cp_async16(sB + (o * SSTR + c4) * 4,
                                       Bp + (size_t)(bx * BN + o) * C_DIM + kk + c4, 16);
                        }
                    }
                    asm volatile("cp.async.mbarrier.arrive.noinc.shared.b64 [%0];"
                                 :: "r"(bar_base + b * 8) : "memory");
                    ++fidx;
                }
            }
        } else {
            // ================= CONSUMERS =================
            const int fc  = lane & 3;
            const int r8  = lane >> 2;
            uint32_t* stg0 = smw + AGG_WORDS;

            for (int bx = 0; bx < 2; ++bx) {
                float acc[4][8][4];
#pragma unroll
                for (int mt = 0; mt < 4; ++mt)
#pragma unroll
                    for (int nt = 0; nt < 8; ++nt)
#pragma unroll
                        for (int i = 0; i < 4; ++i) acc[mt][nt][i] = 0.f;

                for (int c = 0; c < NCH; ++c) {
                    if (c < 16) MBAR_WAIT(bar_base + 32 + c * 8, it & 1);
                    const int b = fidx & 1;
                    MBAR_WAIT(bar_base + b * 8, (fidx >> 1) & 1);

                    uint32_t* as = stg0 + b * STG_WORDS;
                    uint32_t* bs = as + A_WORDS;

                    if (c < 16) {
                        const uint32_t* am = aggw + c * 32;
#pragma unroll
                        for (int ks = 0; ks < 4; ++ks) {
                            const int kb = ks * 8;
                            uint32_t afr[4][4];
#pragma unroll
                            for (int mt = 0; mt < 4; ++mt) {
                                const int r = mt * 16 + r8;
                                afr[mt][0] = am[r * AGSTR + kb + fc];
                                afr[mt][1] = am[(r + 8) * AGSTR + kb + fc];
                                afr[mt][2] = am[r * AGSTR + kb + fc + 4];
                                afr[mt][3] = am[(r + 8) * AGSTR + kb + fc + 4];
                            }
                            uint32_t bfr[8][2];
#pragma unroll
                            for (int nt = 0; nt < 8; ++nt) {
                                const int o = wid * 64 + nt * 8 + r8;
                                bfr[nt][0] = bs[o * SSTR + kb + fc];
                                bfr[nt][1] = bs[o * SSTR + kb + fc + 4];
                            }
#pragma unroll
                            for (int mt = 0; mt < 4; ++mt)
#pragma unroll
                                for (int nt = 0; nt < 8; ++nt)
                                    mma_tf32(acc[mt][nt], afr[mt], bfr[nt]);
                        }
                    } else {
                        const float* af = reinterpret_cast<const float*>(as);
#pragma unroll
                        for (int ks = 0; ks < 4; ++ks) {
                            const int kb = ks * 8;
                            uint32_t afr[4][4];
#pragma unroll
                            for (int mt = 0; mt < 4; ++mt) {
                                const int r = mt * 16 + r8;
                                afr[mt][0] = f2tf32(af[r * SSTR + kb + fc]);
                                afr[mt][1] = f2tf32(af[(r + 8) * SSTR + kb + fc]);
                                afr[mt][2] = f2tf32(af[r * SSTR + kb + fc + 4]);
                                afr[mt][3] = f2tf32(af[(r + 8) * SSTR + kb + fc + 4]);
                            }
                            uint32_t bfr[8][2];
#pragma unroll
                            for (int nt = 0; nt < 8; ++nt) {
                                const int o = wid * 64 + nt * 8 + r8;
                                bfr[nt][0] = bs[o * SSTR + kb + fc];
                                bfr[nt][1] = bs[o * SSTR + kb + fc + 4];
                            }
#pragma unroll
                            for (int mt = 0; mt < 4; ++mt)
#pragma unroll
                                for (int nt = 0; nt < 8; ++nt)
                                    mma_tf32(acc[mt][nt], afr[mt], bfr[nt]);
                        }
                    }
                    MBAR_ARRIVE(bar_base + 16 + b * 8);
                    ++fidx;
                }

                // ---- epilogue for this bx ----
#pragma unroll
                for (int nt = 0; nt < 8; ++nt) {
                    const int col = bx * BN + wid * 64 + nt * 8 + 2 * (lane & 3);
                    const float b0 = __ldg(bl + col)     + __ldg(br + col);
                    const float b1 = __ldg(bl + col + 1) + __ldg(br + col + 1);
#pragma unroll
                    for (int mt = 0; mt < 4; ++mt) {
                        const int row0 = rowBase + mt * 16 + r8;
                        const int row1 = row0 + 8;
                        if (row0 < Nrows) {
                            float2 v = make_float2(acc[mt][nt][0] + b0, acc[mt][nt][1] + b1);
                            *reinterpret_cast<float2*>(out + (size_t)row0 * OUT_DIM + col) = v;
                        }
                        if (row1 < Nrows) {
                            float2 v = make_float2(acc[mt][nt][2] + b0, acc[mt][nt][3] + b1);
                            *reinterpret_cast<float2*>(out + (size_t)row1 * OUT_DIM + col) = v;
                        }
                    }
                }
            }
        }
        __syncthreads();   // agg smem + ready-bar reuse boundary between row-blocks
    }
}

// ---------------------------------------------------------------------------
// Launch
// ---------------------------------------------------------------------------
extern "C" void kernel_launch(void* const* d_in, const int* in_sizes, int n_in,
                              void* d_out, int out_size)
{
    const float* x     = (const float*)d_in[0];
    const float* neigh = (const float*)d_in[1];
    const float* Wl    = (const float*)d_in[2];
    const float* bl    = (const float*)d_in[3];
    const float* Wr    = (const float*)d_in[4];
    const float* br    = (const float*)d_in[5];
    float* out = (float*)d_out;

    const int N    = in_sizes[0] / C_DIM;        // 20000
    const int NBLK = (N + BM - 1) / BM;          // 313

    wconv_kernel<<<512, 256>>>(Wl, Wr);

    static int smem_set = 0;
    if (!smem_set) {
        cudaFuncSetAttribute(fused_kernel, cudaFuncAttributeMaxDynamicSharedMemorySize, SMEM_BYTES);
        smem_set = 1;
    }
    const int grid = (NBLK < 148) ? NBLK : 148;
    fused_kernel<<<grid, THREADS, SMEM_BYTES>>>(x, neigh, bl, br, out, N, NBLK);
}

// round 7
// speedup vs baseline: 1.0908x; 1.0908x over previous
#include <cuda_runtime.h>
#include <cstdint>

// Shape-fixed problem: N=20000, K=32, C=512, OUT=512  (N % 32 == 0)
#define C_DIM   512
#define OUT_DIM 512
#define K_NB    32

#define BM      32            // rows per block-tile (625 blocks)
#define BN      256           // cols per bx pass (2 passes)
#define THREADS 512           // warps 0-7 consumers, 8-15 producers
#define NCH     32            // chunks per bx pass (16 x + 16 agg)

#define AGSTR   516                            // agg row stride (words); r*516 % 32 = 4r
#define AGG1    (BM * AGSTR)                   // 16512 words per agg buffer
#define SSTR    36                             // stage row stride (words); 4r+fc conflict-free
#define A_WORDS (BM * SSTR)                    // 1152
#define B_WORDS (BN * SSTR)                    // 9216
#define STG_WORDS (A_WORDS + B_WORDS)          // 10368
#define STG_OFF  (2 * AGG1)                    // 33024
#define BIAS_OFF (STG_OFF + 2 * STG_WORDS)     // 53760
#define BAR_WOFF (BIAS_OFF + OUT_DIM)          // 54272
#define SMEM_BYTES ((BAR_WOFF + 16) * 4)       // 217152

// tf32-bit weights (pre-converted once per launch)
__device__ uint32_t g_wl[OUT_DIM * C_DIM];
__device__ uint32_t g_wr[OUT_DIM * C_DIM];

__device__ __forceinline__ uint32_t f2tf32(float f) {
    uint32_t r;
    asm("cvt.rna.tf32.f32 %0, %1;" : "=r"(r) : "f"(f));
    return r;
}

__device__ __forceinline__ void mma_tf32(float* c, const uint32_t* a, const uint32_t* b) {
    asm volatile(
        "mma.sync.aligned.m16n8k8.row.col.f32.tf32.tf32.f32 "
        "{%0,%1,%2,%3}, {%4,%5,%6,%7}, {%8,%9}, {%0,%1,%2,%3};"
        : "+f"(c[0]), "+f"(c[1]), "+f"(c[2]), "+f"(c[3])
        : "r"(a[0]), "r"(a[1]), "r"(a[2]), "r"(a[3]), "r"(b[0]), "r"(b[1]));
}

__device__ __forceinline__ void cp_async16(uint32_t saddr, const void* gsrc, int src_bytes) {
    asm volatile("cp.async.cg.shared.global [%0], [%1], 16, %2;\n"
                 :: "r"(saddr), "l"(gsrc), "r"(src_bytes));
}

#define MBAR_INIT(addr, cnt) \
    asm volatile("mbarrier.init.shared.b64 [%0], %1;" :: "r"(addr), "r"((uint32_t)(cnt)) : "memory")
#define MBAR_ARRIVE(addr) \
    asm volatile("mbarrier.arrive.release.cta.shared::cta.b64 _, [%0];" :: "r"(addr) : "memory")
#define MBAR_WAIT(addr, par) do { \
    uint32_t _m = (addr); uint32_t _p = (uint32_t)(par); uint32_t _done; \
    asm volatile("{\n\t.reg .pred p;\n\t" \
        "mbarrier.try_wait.parity.acquire.cta.shared::cta.b64 p, [%1], %2;\n\t" \
        "selp.b32 %0, 1, 0, p;\n\t}" : "=r"(_done) : "r"(_m), "r"(_p) : "memory"); \
    if (!_done) { \
        asm volatile("{\n\t.reg .pred P1;\n\t" \
            "WL_%=:\n\t" \
            "mbarrier.try_wait.parity.acquire.cta.shared::cta.b64 P1, [%0], %1, 0x989680;\n\t" \
            "@P1 bra.uni WD_%=;\n\t" \
            "bra.uni WL_%=;\n\t" \
            "WD_%=:\n\t}" :: "r"(_m), "r"(_p) : "memory"); \
    } } while (0)

#define CBAR() asm volatile("bar.sync 1, 256;" ::: "memory")   // consumer-group barrier

// ---------------------------------------------------------------------------
// W pre-conversion: fp32 -> tf32 bits
// ---------------------------------------------------------------------------
__global__ void __launch_bounds__(256) wconv_kernel(const float* __restrict__ wl,
                                                    const float* __restrict__ wr)
{
    int i = blockIdx.x * 256 + threadIdx.x;        // 0..131071 (float4 units)
    const bool isL = (i < 65536);
    int j = isL ? i : i - 65536;
    float4 v = reinterpret_cast<const float4*>(isL ? wl : wr)[j];
    uint4 o;
    o.x = f2tf32(v.x); o.y = f2tf32(v.y); o.z = f2tf32(v.z); o.w = f2tf32(v.w);
    reinterpret_cast<uint4*>(isL ? g_wl : g_wr)[j] = o;
}

// ---------------------------------------------------------------------------
// Fused persistent kernel.
//   warps 8-15 (256 thr): stream neigh_x -> mean -> tf32 agg smem (double-buffered)
//   warps 0-7  (256 thr): dual tf32 GEMM, self-loaded cp.async stages
// Per row-block (32 rows): bx0 = [x/Wl c0-15, agg/Wr c16-31],
//                          bx1 = [agg/Wr c0-15 (free-arrive at c15), x/Wl c16-31]
// ---------------------------------------------------------------------------
__global__ void __launch_bounds__(THREADS, 1)
fused_kernel(const float* __restrict__ x,
             const float* __restrict__ nx,
             const float* __restrict__ bl,
             const float* __restrict__ br,
             float* __restrict__ out,
             int Nrows, int NBLK)
{
    extern __shared__ uint32_t smw[];
    const uint32_t smem_u32 = (uint32_t)__cvta_generic_to_shared(smw);
    const uint32_t stg_base = smem_u32 + STG_OFF * 4;
    const uint32_t bar_base = smem_u32 + BAR_WOFF * 4;
    // bars: ready[b] = bar_base + b*8 ; free[b] = bar_base + 16 + b*8
    float* bias = reinterpret_cast<float*>(smw + BIAS_OFF);

    const int tid  = threadIdx.x;
    const int lane = tid & 31;
    const int wid  = tid >> 5;

    if (tid == 0) {
        MBAR_INIT(bar_base + 0, 256);  MBAR_INIT(bar_base + 8, 256);   // ready
        MBAR_INIT(bar_base + 16, 256); MBAR_INIT(bar_base + 24, 256);  // free
    }
    bias[tid & 511] = bl[tid & 511] + br[tid & 511];
    __syncthreads();

    int it = 0;
    for (int blk = blockIdx.x; blk < NBLK; blk += gridDim.x, ++it) {
        const int rowBase = blk * BM;
        const int b = it & 1;

        if (wid >= 8) {
            // ===================== PRODUCERS =====================
            const int ptid = tid - 256;          // 0..255
            const int prow = ptid >> 3;          // 0..31
            const int oct  = ptid & 7;           // 16B slot within 128B line

            if (it >= 2) MBAR_WAIT(bar_base + 16 + b * 8, ((it >> 1) - 1) & 1);

            const int grow = rowBase + prow;
            const float inv = 1.0f / (float)K_NB;

            // Two half-passes: half h covers columns h*256 + oct*4 + 32*j, j=0..7
            // (full 512-column coverage; 8 accumulators = 32 regs per pass)
#pragma unroll
            for (int h = 0; h < 2; ++h) {
                float4 s[8];
#pragma unroll
                for (int j = 0; j < 8; ++j) s[j] = make_float4(0.f, 0.f, 0.f, 0.f);
                if (grow < Nrows) {
                    const float* base = nx + (size_t)grow * (K_NB * C_DIM)
                                      + h * 256 + oct * 4;
#pragma unroll 2
                    for (int nb = 0; nb < K_NB; ++nb) {
                        const float* p = base + nb * C_DIM;
#pragma unroll
                        for (int j = 0; j < 8; ++j) {
                            float4 v = *reinterpret_cast<const float4*>(p + 32 * j);
                            s[j].x += v.x; s[j].y += v.y; s[j].z += v.z; s[j].w += v.w;
                        }
                    }
                }
                uint32_t* d = smw + b * AGG1 + prow * AGSTR + h * 256 + oct * 4;
#pragma unroll
                for (int j = 0; j < 8; ++j) {
                    uint4 o;
                    o.x = f2tf32(s[j].x * inv); o.y = f2tf32(s[j].y * inv);
                    o.z = f2tf32(s[j].z * inv); o.w = f2tf32(s[j].w * inv);
                    *reinterpret_cast<uint4*>(d + 32 * j) = o;
                }
            }

            MBAR_ARRIVE(bar_base + b * 8);
        } else {
            // ===================== CONSUMERS =====================
            const int fc = lane & 3;
            const int r8 = lane >> 2;

            for (int bx = 0; bx < 2; ++bx) {
                float acc[2][4][4];
#pragma unroll
                for (int mt = 0; mt < 2; ++mt)
#pragma unroll
                    for (int nt = 0; nt < 4; ++nt)
#pragma unroll
                        for (int i = 0; i < 4; ++i) acc[mt][nt][i] = 0.f;

                // chunk c: is_x = (bx==0) ? c<16 : c>=16 ; kk=(c&15)*32
                auto issue = [&](int c) {
                    const int fb = c & 1;
                    const bool is_x = (bx == 0) ? (c < 16) : (c >= 16);
                    const int kk = (c & 15) * 32;
                    const uint32_t sA = stg_base + fb * STG_WORDS * 4;
                    const uint32_t sB = sA + A_WORDS * 4;
                    if (is_x) {
                        int r = tid >> 3, c4 = (tid & 7) * 4;
                        int grow = rowBase + r;
                        cp_async16(sA + (r * SSTR + c4) * 4,
                                   x + (size_t)grow * C_DIM + kk + c4,
                                   (grow < Nrows) ? 16 : 0);
                    }
                    const uint32_t* Bp = is_x ? g_wl : g_wr;
#pragma unroll
                    for (int i = 0; i < 8; ++i) {
                        int idx = i * 256 + tid;       // 0..2047
                        int o = idx >> 3, c4 = (idx & 7) * 4;
                        cp_async16(sB + (o * SSTR + c4) * 4,
                                   Bp + (size_t)(bx * BN + o) * C_DIM + kk + c4, 16);
                    }
                    asm volatile("cp.async.commit_group;\n");
                };

                issue(0); issue(1);
                for (int c = 0; c < NCH; ++c) {
                    // first agg use of this row-block: wait producer
                    if (bx == 0 && c == 16) MBAR_WAIT(bar_base + b * 8, (it >> 1) & 1);

                    if (c < NCH - 1) asm volatile("cp.async.wait_group 1;\n");
                    else             asm volatile("cp.async.wait_group 0;\n");
                    CBAR();                              // chunk c data visible to all

                    const int fb = c & 1;
                    const bool is_x = (bx == 0) ? (c < 16) : (c >= 16);
                    uint32_t* stg = smw + STG_OFF + fb * STG_WORDS;
                    const uint32_t* bs = stg + A_WORDS;
                    const float*    af = reinterpret_cast<const float*>(stg);
                    const uint32_t* am = smw + b * AGG1 + (c & 15) * 32;

#pragma unroll
                    for (int ks = 0; ks < 4; ++ks) {
                        const int kb = ks * 8;
                        uint32_t afr[2][4];
                        if (is_x) {
#pragma unroll
                            for (int mt = 0; mt < 2; ++mt) {
                                const int r = mt * 16 + r8;
                                afr[mt][0] = f2tf32(af[r * SSTR + kb + fc]);
                                afr[mt][1] = f2tf32(af[(r + 8) * SSTR + kb + fc]);
                                afr[mt][2] = f2tf32(af[r * SSTR + kb + fc + 4]);
                                afr[mt][3] = f2tf32(af[(r + 8) * SSTR + kb + fc + 4]);
                            }
                        } else {
#pragma unroll
                            for (int mt = 0; mt < 2; ++mt) {
                                const int r = mt * 16 + r8;
                                afr[mt][0] = am[r * AGSTR + kb + fc];
                                afr[mt][1] = am[(r + 8) * AGSTR + kb + fc];
                                afr[mt][2] = am[r * AGSTR + kb + fc + 4];
                                afr[mt][3] = am[(r + 8) * AGSTR + kb + fc + 4];
                            }
                        }
                        uint32_t bfr[4][2];
#pragma unroll
                        for (int nt = 0; nt < 4; ++nt) {
                            const int o = wid * 32 + nt * 8 + r8;
                            bfr[nt][0] = bs[o * SSTR + kb + fc];
                            bfr[nt][1] = bs[o * SSTR + kb + fc + 4];
                        }
#pragma unroll
                        for (int mt = 0; mt < 2; ++mt)
#pragma unroll
                            for (int nt = 0; nt < 4; ++nt)
                                mma_tf32(acc[mt][nt], afr[mt], bfr[nt]);
                    }

                    // last agg read of this row-block -> release agg buffer
                    if (bx == 1 && c == 15) MBAR_ARRIVE(bar_base + 16 + b * 8);

                    if (c + 2 < NCH) { CBAR(); issue(c + 2); }
                }
                CBAR();    // all stage reads done before next bx reissues

                // ---- epilogue for this bx ----
#pragma unroll
                for (int nt = 0; nt < 4; ++nt) {
                    const int col = bx * BN + wid * 32 + nt * 8 + 2 * (lane & 3);
                    const float b0 = bias[col], b1 = bias[col + 1];
#pragma unroll
                    for (int mt = 0; mt < 2; ++mt) {
                        const int row0 = rowBase + mt * 16 + r8;
                        const int row1 = row0 + 8;
                        if (row0 < Nrows) {
                            float2 v = make_float2(acc[mt][nt][0] + b0, acc[mt][nt][1] + b1);
                            *reinterpret_cast<float2*>(out + (size_t)row0 * OUT_DIM + col) = v;
                        }
                        if (row1 < Nrows) {
                            float2 v = make_float2(acc[mt][nt][2] + b0, acc[mt][nt][3] + b1);
                            *reinterpret_cast<float2*>(out + (size_t)row1 * OUT_DIM + col) = v;
                        }
                    }
                }
            }
        }
        // no __syncthreads: ready/free mbarriers carry all cross-role ordering
    }
}

// ---------------------------------------------------------------------------
// Launch
// ---------------------------------------------------------------------------
extern "C" void kernel_launch(void* const* d_in, const int* in_sizes, int n_in,
                              void* d_out, int out_size)
{
    const float* x     = (const float*)d_in[0];
    const float* neigh = (const float*)d_in[1];
    const float* Wl    = (const float*)d_in[2];
    const float* bl    = (const float*)d_in[3];
    const float* Wr    = (const float*)d_in[4];
    const float* br    = (const float*)d_in[5];
    float* out = (float*)d_out;

    const int N    = in_sizes[0] / C_DIM;      // 20000
    const int NBLK = (N + BM - 1) / BM;        // 625

    wconv_kernel<<<512, 256>>>(Wl, Wr);

    static int smem_set = 0;
    if (!smem_set) {
        cudaFuncSetAttribute(fused_kernel, cudaFuncAttributeMaxDynamicSharedMemorySize, SMEM_BYTES);
        smem_set = 1;
    }
    const int grid = (NBLK < 148) ? NBLK : 148;
    fused_kernel<<<grid, THREADS, SMEM_BYTES>>>(x, neigh, bl, br, out, N, NBLK);
}

// round 8
// speedup vs baseline: 1.4731x; 1.3505x over previous
#include <cuda_runtime.h>
#include <cstdint>

// Shape-fixed problem: N=20000, K=32, C=512, OUT=512
#define C_DIM   512
#define OUT_DIM 512
#define K_NB    32
#define N_MAX   20000

// GEMM tiling: block 128x128, 8 warps of 32x64, BK=32, 3-stage cp.async
#define BM       128
#define BN       128
#define BK       32
#define SSTR     36                       // padded smem row stride (words)
#define NSTAGE   3
#define THREADS  256
#define A_WORDS  (BM * SSTR)              // 4608
#define B_WORDS  (BN * SSTR)              // 4608
#define STG_WORDS (A_WORDS + B_WORDS)     // 9216
#define SMEM_BYTES (NSTAGE * STG_WORDS * 4)   // 110592

// tf32-bit scratch
__device__ uint32_t g_agg[(size_t)N_MAX * C_DIM];   // mean(neigh_x) as tf32 bits
__device__ uint32_t g_wl [OUT_DIM * C_DIM];
__device__ uint32_t g_wr [OUT_DIM * C_DIM];

__device__ __forceinline__ uint32_t f2tf32(float f) {
    uint32_t r;
    asm("cvt.rna.tf32.f32 %0, %1;" : "=r"(r) : "f"(f));
    return r;
}

// ---------------------------------------------------------------------------
// Kernel 1: mean over neighbor axis -> tf32 bits.  (HBM-bound, at floor)
// One block per node, 128 threads, each owns one float4 of C.
// ---------------------------------------------------------------------------
__global__ void __launch_bounds__(128) mean_kernel(const float* __restrict__ nx, int N)
{
    int n  = blockIdx.x;
    int c4 = threadIdx.x;
    const float4* p = reinterpret_cast<const float4*>(nx + (size_t)n * K_NB * C_DIM) + c4;
    float4 s = make_float4(0.f, 0.f, 0.f, 0.f);
#pragma unroll 8
    for (int k = 0; k < K_NB; ++k) {
        float4 v = p[(size_t)k * (C_DIM / 4)];
        s.x += v.x; s.y += v.y; s.z += v.z; s.w += v.w;
    }
    const float inv = 1.0f / (float)K_NB;
    uint4 o;
    o.x = f2tf32(s.x * inv); o.y = f2tf32(s.y * inv);
    o.z = f2tf32(s.z * inv); o.w = f2tf32(s.w * inv);
    reinterpret_cast<uint4*>(g_agg + (size_t)n * C_DIM)[c4] = o;
}

// ---------------------------------------------------------------------------
// Kernel 2: W fp32 -> tf32 bits (one-shot, ~4 us)
// ---------------------------------------------------------------------------
__global__ void __launch_bounds__(256) wconv_kernel(const float* __restrict__ wl,
                                                    const float* __restrict__ wr)
{
    int i = blockIdx.x * 256 + threadIdx.x;        // float4 units, 0..131071
    const bool isL = (i < 65536);
    int j = isL ? i : i - 65536;
    float4 v = reinterpret_cast<const float4*>(isL ? wl : wr)[j];
    uint4 o;
    o.x = f2tf32(v.x); o.y = f2tf32(v.y); o.z = f2tf32(v.z); o.w = f2tf32(v.w);
    reinterpret_cast<uint4*>(isL ? g_wl : g_wr)[j] = o;
}

// ---------------------------------------------------------------------------
// GEMM helpers
// ---------------------------------------------------------------------------
__device__ __forceinline__ void mma_tf32(float* c, const uint32_t* a, const uint32_t* b) {
    asm volatile(
        "mma.sync.aligned.m16n8k8.row.col.f32.tf32.tf32.f32 "
        "{%0,%1,%2,%3}, {%4,%5,%6,%7}, {%8,%9}, {%0,%1,%2,%3};"
        : "+f"(c[0]), "+f"(c[1]), "+f"(c[2]), "+f"(c[3])
        : "r"(a[0]), "r"(a[1]), "r"(a[2]), "r"(a[3]), "r"(b[0]), "r"(b[1]));
}

__device__ __forceinline__ void cp_async16(uint32_t saddr, const void* gsrc, int src_bytes) {
    asm volatile("cp.async.cg.shared.global [%0], [%1], 16, %2;\n"
                 :: "r"(saddr), "l"(gsrc), "r"(src_bytes));
}

// ---------------------------------------------------------------------------
// Kernel 3: out = x @ Wl^T + agg @ Wr^T + (bl + br)
// Concatenated K = 1024: chunks 0-15 = x (fp32, CVT in-reg) / Wl,
//                        chunks 16-31 = agg (tf32 bits) / Wr.
// Grid (4, 157) = 628 CTAs, 2 CTAs/SM.
// ---------------------------------------------------------------------------
__global__ void __launch_bounds__(THREADS, 2)
gemm_kernel(const float* __restrict__ x,
            const float* __restrict__ bl, const float* __restrict__ br,
            float* __restrict__ out, int Nrows)
{
    extern __shared__ uint32_t smem[];
    const uint32_t smem_u32 = (uint32_t)__cvta_generic_to_shared(smem);

    const int tid  = threadIdx.x;
    const int lane = tid & 31;
    const int warp = tid >> 5;
    const int wm   = warp & 3;                 // 4 row groups of 32
    const int wn   = warp >> 2;                // 2 col groups of 64
    const int rowBase = blockIdx.y * BM;
    const int colBase = blockIdx.x * BN;

    const int fc = lane & 3;
    const int r8 = lane >> 2;

    float acc[2][8][4];
#pragma unroll
    for (int mt = 0; mt < 2; ++mt)
#pragma unroll
        for (int nt = 0; nt < 8; ++nt)
#pragma unroll
            for (int i = 0; i < 4; ++i) acc[mt][nt][i] = 0.f;

    // ---- chunk loader: A[128,32] + B[128,32] ----
    auto issue = [&](int ch) {
        const int s = ch % NSTAGE;
        const uint32_t sA = smem_u32 + (s * STG_WORDS) * 4;
        const uint32_t sB = sA + A_WORDS * 4;
        const bool is_x = (ch < 16);
        const int kk = (ch & 15) * BK;
#pragma unroll
        for (int i = 0; i < 4; ++i) {                 // A: 128 x 32
            int idx = i * THREADS + tid;              // 0..1023
            int r = idx >> 3, c4 = (idx & 7) * 4;
            int grow = rowBase + r;
            const void* g = is_x
                ? (const void*)(x + (size_t)grow * C_DIM + kk + c4)
                : (const void*)(g_agg + (size_t)grow * C_DIM + kk + c4);
            cp_async16(sA + (r * SSTR + c4) * 4, g, (grow < Nrows) ? 16 : 0);
        }
        const uint32_t* Bp = is_x ? g_wl : g_wr;
#pragma unroll
        for (int i = 0; i < 4; ++i) {                 // B: 128 x 32
            int idx = i * THREADS + tid;
            int o = idx >> 3, c4 = (idx & 7) * 4;
            cp_async16(sB + (o * SSTR + c4) * 4,
                       Bp + (size_t)(colBase + o) * C_DIM + kk + c4, 16);
        }
        asm volatile("cp.async.commit_group;\n");
    };

    issue(0); issue(1);
    for (int t = 0; t < 32; ++t) {
        if (t + 2 < 32) {
            issue(t + 2);                              // stage freed at end of t-1
            asm volatile("cp.async.wait_group 2;\n");
        } else if (t + 2 == 32) {
            asm volatile("cp.async.wait_group 1;\n");
        } else {
            asm volatile("cp.async.wait_group 0;\n");
        }
        __syncthreads();                               // chunk t visible to all

        const uint32_t* as = smem + (t % NSTAGE) * STG_WORDS;
        const uint32_t* bs = as + A_WORDS;
        const float*    af = reinterpret_cast<const float*>(as);
        const bool is_x = (t < 16);

#pragma unroll
        for (int ks = 0; ks < 4; ++ks) {
            const int kb = ks * 8;
            uint32_t afr[2][4];
            if (is_x) {
#pragma unroll
                for (int mt = 0; mt < 2; ++mt) {
                    const int r = wm * 32 + mt * 16 + r8;
                    afr[mt][0] = f2tf32(af[r * SSTR + kb + fc]);
                    afr[mt][1] = f2tf32(af[(r + 8) * SSTR + kb + fc]);
                    afr[mt][2] = f2tf32(af[r * SSTR + kb + fc + 4]);
                    afr[mt][3] = f2tf32(af[(r + 8) * SSTR + kb + fc + 4]);
                }
            } else {
#pragma unroll
                for (int mt = 0; mt < 2; ++mt) {
                    const int r = wm * 32 + mt * 16 + r8;
                    afr[mt][0] = as[r * SSTR + kb + fc];
                    afr[mt][1] = as[(r + 8) * SSTR + kb + fc];
                    afr[mt][2] = as[r * SSTR + kb + fc + 4];
                    afr[mt][3] = as[(r + 8) * SSTR + kb + fc + 4];
                }
            }
            uint32_t bfr[8][2];
#pragma unroll
            for (int nt = 0; nt < 8; ++nt) {
                const int o = wn * 64 + nt * 8 + r8;
                bfr[nt][0] = bs[o * SSTR + kb + fc];
                bfr[nt][1] = bs[o * SSTR + kb + fc + 4];
            }
#pragma unroll
            for (int mt = 0; mt < 2; ++mt)
#pragma unroll
                for (int nt = 0; nt < 8; ++nt)
                    mma_tf32(acc[mt][nt], afr[mt], bfr[nt]);
        }
        __syncthreads();                               // stage reuse boundary
    }

    // ---- epilogue: fused bias via __ldg, fp32 store ----
#pragma unroll
    for (int nt = 0; nt < 8; ++nt) {
        const int col = colBase + wn * 64 + nt * 8 + 2 * (lane & 3);
        const float b0 = __ldg(bl + col)     + __ldg(br + col);
        const float b1 = __ldg(bl + col + 1) + __ldg(br + col + 1);
#pragma unroll
        for (int mt = 0; mt < 2; ++mt) {
            const int row0 = rowBase + wm * 32 + mt * 16 + r8;
            const int row1 = row0 + 8;
            if (row0 < Nrows) {
                float2 v = make_float2(acc[mt][nt][0] + b0, acc[mt][nt][1] + b1);
                *reinterpret_cast<float2*>(out + (size_t)row0 * OUT_DIM + col) = v;
            }
            if (row1 < Nrows) {
                float2 v = make_float2(acc[mt][nt][2] + b0, acc[mt][nt][3] + b1);
                *reinterpret_cast<float2*>(out + (size_t)row1 * OUT_DIM + col) = v;
            }
        }
    }
}

// ---------------------------------------------------------------------------
// Launch
// ---------------------------------------------------------------------------
extern "C" void kernel_launch(void* const* d_in, const int* in_sizes, int n_in,
                              void* d_out, int out_size)
{
    const float* x     = (const float*)d_in[0];
    const float* neigh = (const float*)d_in[1];
    const float* Wl    = (const float*)d_in[2];
    const float* bl    = (const float*)d_in[3];
    const float* Wr    = (const float*)d_in[4];
    const float* br    = (const float*)d_in[5];
    float* out = (float*)d_out;

    const int N = in_sizes[0] / C_DIM;        // 20000

    mean_kernel<<<N, 128>>>(neigh, N);
    wconv_kernel<<<512, 256>>>(Wl, Wr);

    static int smem_set = 0;
    if (!smem_set) {
        cudaFuncSetAttribute(gemm_kernel, cudaFuncAttributeMaxDynamicSharedMemorySize, SMEM_BYTES);
        smem_set = 1;
    }
    dim3 grid(OUT_DIM / BN, (N + BM - 1) / BM);   // (4, 157) = 628 CTAs
    gemm_kernel<<<grid, THREADS, SMEM_BYTES>>>(x, bl, br, out, N);
}

// round 9
// speedup vs baseline: 1.4801x; 1.0047x over previous
#include <cuda_runtime.h>
#include <cstdint>

// Shape-fixed problem: N=20000, K=32, C=512, OUT=512
#define C_DIM   512
#define OUT_DIM 512
#define K_NB    32
#define N_MAX   20000

// GEMM tiling: block 128x128, 8 warps of 32x64, BK=32, 3-stage cp.async
#define BM       128
#define BN       128
#define BK       32
#define SSTR     36                       // padded smem row stride (words)
#define NSTAGE   3
#define THREADS  256
#define A_WORDS  (BM * SSTR)              // 4608
#define B_WORDS  (BN * SSTR)              // 4608
#define STG_WORDS (A_WORDS + B_WORDS)     // 9216
#define SMEM_BYTES (NSTAGE * STG_WORDS * 4)   // 110592

// tf32-bit scratch
__device__ uint32_t g_agg[(size_t)N_MAX * C_DIM];   // mean(neigh_x) as tf32 bits
__device__ uint32_t g_wl [OUT_DIM * C_DIM];
__device__ uint32_t g_wr [OUT_DIM * C_DIM];

__device__ __forceinline__ uint32_t f2tf32(float f) {
    uint32_t r;
    asm("cvt.rna.tf32.f32 %0, %1;" : "=r"(r) : "f"(f));
    return r;
}

// ---------------------------------------------------------------------------
// Kernel 1: mean over neighbor axis -> tf32 bits.  (HBM-bound, at floor)
// One block per node, 128 threads, each owns one float4 of C.
// ---------------------------------------------------------------------------
__global__ void __launch_bounds__(128) mean_kernel(const float* __restrict__ nx, int N)
{
    int n  = blockIdx.x;
    int c4 = threadIdx.x;
    const float4* p = reinterpret_cast<const float4*>(nx + (size_t)n * K_NB * C_DIM) + c4;
    float4 s = make_float4(0.f, 0.f, 0.f, 0.f);
#pragma unroll 8
    for (int k = 0; k < K_NB; ++k) {
        float4 v = p[(size_t)k * (C_DIM / 4)];
        s.x += v.x; s.y += v.y; s.z += v.z; s.w += v.w;
    }
    const float inv = 1.0f / (float)K_NB;
    uint4 o;
    o.x = f2tf32(s.x * inv); o.y = f2tf32(s.y * inv);
    o.z = f2tf32(s.z * inv); o.w = f2tf32(s.w * inv);
    reinterpret_cast<uint4*>(g_agg + (size_t)n * C_DIM)[c4] = o;
}

// ---------------------------------------------------------------------------
// Kernel 2: W fp32 -> tf32 bits (one-shot, ~4 us)
// ---------------------------------------------------------------------------
__global__ void __launch_bounds__(256) wconv_kernel(const float* __restrict__ wl,
                                                    const float* __restrict__ wr)
{
    int i = blockIdx.x * 256 + threadIdx.x;        // float4 units, 0..131071
    const bool isL = (i < 65536);
    int j = isL ? i : i - 65536;
    float4 v = reinterpret_cast<const float4*>(isL ? wl : wr)[j];
    uint4 o;
    o.x = f2tf32(v.x); o.y = f2tf32(v.y); o.z = f2tf32(v.z); o.w = f2tf32(v.w);
    reinterpret_cast<uint4*>(isL ? g_wl : g_wr)[j] = o;
}

// ---------------------------------------------------------------------------
// GEMM helpers
// ---------------------------------------------------------------------------
__device__ __forceinline__ void mma_tf32(float* c, const uint32_t* a, const uint32_t* b) {
    asm volatile(
        "mma.sync.aligned.m16n8k8.row.col.f32.tf32.tf32.f32 "
        "{%0,%1,%2,%3}, {%4,%5,%6,%7}, {%8,%9}, {%0,%1,%2,%3};"
        : "+f"(c[0]), "+f"(c[1]), "+f"(c[2]), "+f"(c[3])
        : "r"(a[0]), "r"(a[1]), "r"(a[2]), "r"(a[3]), "r"(b[0]), "r"(b[1]));
}

__device__ __forceinline__ void cp_async16(uint32_t saddr, const void* gsrc, int src_bytes) {
    asm volatile("cp.async.cg.shared.global [%0], [%1], 16, %2;\n"
                 :: "r"(saddr), "l"(gsrc), "r"(src_bytes));
}

// ---------------------------------------------------------------------------
// Kernel 3: out = x @ Wl^T + agg @ Wr^T + (bl + br)
// Concatenated K = 1024: chunks 0-15 = x (fp32, CVT in-reg) / Wl,
//                        chunks 16-31 = agg (tf32 bits) / Wr.
// Grid (4, 157) = 628 CTAs, 2 CTAs/SM.
// ---------------------------------------------------------------------------
__global__ void __launch_bounds__(THREADS, 2)
gemm_kernel(const float* __restrict__ x,
            const float* __restrict__ bl, const float* __restrict__ br,
            float* __restrict__ out, int Nrows)
{
    extern __shared__ uint32_t smem[];
    const uint32_t smem_u32 = (uint32_t)__cvta_generic_to_shared(smem);

    const int tid  = threadIdx.x;
    const int lane = tid & 31;
    const int warp = tid >> 5;
    const int wm   = warp & 3;                 // 4 row groups of 32
    const int wn   = warp >> 2;                // 2 col groups of 64
    const int rowBase = blockIdx.y * BM;
    const int colBase = blockIdx.x * BN;

    const int fc = lane & 3;
    const int r8 = lane >> 2;

    float acc[2][8][4];
#pragma unroll
    for (int mt = 0; mt < 2; ++mt)
#pragma unroll
        for (int nt = 0; nt < 8; ++nt)
#pragma unroll
            for (int i = 0; i < 4; ++i) acc[mt][nt][i] = 0.f;

    // ---- chunk loader: A[128,32] + B[128,32] ----
    auto issue = [&](int ch) {
        const int s = ch % NSTAGE;
        const uint32_t sA = smem_u32 + (s * STG_WORDS) * 4;
        const uint32_t sB = sA + A_WORDS * 4;
        const bool is_x = (ch < 16);
        const int kk = (ch & 15) * BK;
#pragma unroll
        for (int i = 0; i < 4; ++i) {                 // A: 128 x 32
            int idx = i * THREADS + tid;              // 0..1023
            int r = idx >> 3, c4 = (idx & 7) * 4;
            int grow = rowBase + r;
            const void* g = is_x
                ? (const void*)(x + (size_t)grow * C_DIM + kk + c4)
                : (const void*)(g_agg + (size_t)grow * C_DIM + kk + c4);
            cp_async16(sA + (r * SSTR + c4) * 4, g, (grow < Nrows) ? 16 : 0);
        }
        const uint32_t* Bp = is_x ? g_wl : g_wr;
#pragma unroll
        for (int i = 0; i < 4; ++i) {                 // B: 128 x 32
            int idx = i * THREADS + tid;
            int o = idx >> 3, c4 = (idx & 7) * 4;
            cp_async16(sB + (o * SSTR + c4) * 4,
                       Bp + (size_t)(colBase + o) * C_DIM + kk + c4, 16);
        }
        asm volatile("cp.async.commit_group;\n");
    };

    issue(0); issue(1);
    for (int t = 0; t < 32; ++t) {
        if (t + 2 < 32) {
            issue(t + 2);                              // stage freed at end of t-1
            asm volatile("cp.async.wait_group 2;\n");
        } else if (t + 2 == 32) {
            asm volatile("cp.async.wait_group 1;\n");
        } else {
            asm volatile("cp.async.wait_group 0;\n");
        }
        __syncthreads();                               // chunk t visible to all

        const uint32_t* as = smem + (t % NSTAGE) * STG_WORDS;
        const uint32_t* bs = as + A_WORDS;
        const float*    af = reinterpret_cast<const float*>(as);
        const bool is_x = (t < 16);

#pragma unroll
        for (int ks = 0; ks < 4; ++ks) {
            const int kb = ks * 8;
            uint32_t afr[2][4];
            if (is_x) {
#pragma unroll
                for (int mt = 0; mt < 2; ++mt) {
                    const int r = wm * 32 + mt * 16 + r8;
                    afr[mt][0] = f2tf32(af[r * SSTR + kb + fc]);
                    afr[mt][1] = f2tf32(af[(r + 8) * SSTR + kb + fc]);
                    afr[mt][2] = f2tf32(af[r * SSTR + kb + fc + 4]);
                    afr[mt][3] = f2tf32(af[(r + 8) * SSTR + kb + fc + 4]);
                }
            } else {
#pragma unroll
                for (int mt = 0; mt < 2; ++mt) {
                    const int r = wm * 32 + mt * 16 + r8;
                    afr[mt][0] = as[r * SSTR + kb + fc];
                    afr[mt][1] = as[(r + 8) * SSTR + kb + fc];
                    afr[mt][2] = as[r * SSTR + kb + fc + 4];
                    afr[mt][3] = as[(r + 8) * SSTR + kb + fc + 4];
                }
            }
            uint32_t bfr[8][2];
#pragma unroll
            for (int nt = 0; nt < 8; ++nt) {
                const int o = wn * 64 + nt * 8 + r8;
                bfr[nt][0] = bs[o * SSTR + kb + fc];
                bfr[nt][1] = bs[o * SSTR + kb + fc + 4];
            }
#pragma unroll
            for (int mt = 0; mt < 2; ++mt)
#pragma unroll
                for (int nt = 0; nt < 8; ++nt)
                    mma_tf32(acc[mt][nt], afr[mt], bfr[nt]);
        }
        __syncthreads();                               // stage reuse boundary
    }

    // ---- epilogue: fused bias via __ldg, fp32 store ----
#pragma unroll
    for (int nt = 0; nt < 8; ++nt) {
        const int col = colBase + wn * 64 + nt * 8 + 2 * (lane & 3);
        const float b0 = __ldg(bl + col)     + __ldg(br + col);
        const float b1 = __ldg(bl + col + 1) + __ldg(br + col + 1);
#pragma unroll
        for (int mt = 0; mt < 2; ++mt) {
            const int row0 = rowBase + wm * 32 + mt * 16 + r8;
            const int row1 = row0 + 8;
            if (row0 < Nrows) {
                float2 v = make_float2(acc[mt][nt][0] + b0, acc[mt][nt][1] + b1);
                *reinterpret_cast<float2*>(out + (size_t)row0 * OUT_DIM + col) = v;
            }
            if (row1 < Nrows) {
                float2 v = make_float2(acc[mt][nt][2] + b0, acc[mt][nt][3] + b1);
                *reinterpret_cast<float2*>(out + (size_t)row1 * OUT_DIM + col) = v;
            }
        }
    }
}

// ---------------------------------------------------------------------------
// Launch
// ---------------------------------------------------------------------------
extern "C" void kernel_launch(void* const* d_in, const int* in_sizes, int n_in,
                              void* d_out, int out_size)
{
    const float* x     = (const float*)d_in[0];
    const float* neigh = (const float*)d_in[1];
    const float* Wl    = (const float*)d_in[2];
    const float* bl    = (const float*)d_in[3];
    const float* Wr    = (const float*)d_in[4];
    const float* br    = (const float*)d_in[5];
    float* out = (float*)d_out;

    const int N = in_sizes[0] / C_DIM;        // 20000

    mean_kernel<<<N, 128>>>(neigh, N);
    wconv_kernel<<<512, 256>>>(Wl, Wr);

    static int smem_set = 0;
    if (!smem_set) {
        cudaFuncSetAttribute(gemm_kernel, cudaFuncAttributeMaxDynamicSharedMemorySize, SMEM_BYTES);
        smem_set = 1;
    }
    dim3 grid(OUT_DIM / BN, (N + BM - 1) / BM);   // (4, 157) = 628 CTAs
    gemm_kernel<<<grid, THREADS, SMEM_BYTES>>>(x, bl, br, out, N);
}

// round 10
// speedup vs baseline: 1.7146x; 1.1584x over previous
#include <cuda_runtime.h>
#include <cstdint>

// Shape-fixed problem: N=20000, K=32, C=512, OUT=512
#define C_DIM   512
#define OUT_DIM 512
#define K_NB    32
#define N_MAX   20000

#define BM       128
#define BN       128
#define BK       32
#define SSTR     36                        // padded smem row stride (words)
#define THREADS  256
#define A_WORDS  (BM * SSTR)               // 4608
#define B_WORDS  (BN * SSTR)               // 4608
#define STG_WORDS (A_WORDS + B_WORDS)      // 9216
#define NCH      16                        // K=512 per GEMM half

#define SMEM_COMBO (2 * STG_WORDS * 4)     // 73728  (2-stage, x-GEMM)
#define SMEM_AGG   (3 * STG_WORDS * 4)     // 110592 (3-stage, agg-GEMM)

#define GEMM_CTAS 628                      // (OUT/BN) * ceil(N/BM) = 4 * 157

// tf32-bit scratch
__device__ uint32_t g_agg[(size_t)N_MAX * C_DIM];   // mean(neigh_x) as tf32 bits
__device__ uint32_t g_wl [OUT_DIM * C_DIM];
__device__ uint32_t g_wr [OUT_DIM * C_DIM];

__device__ __forceinline__ uint32_t f2tf32(float f) {
    uint32_t r;
    asm("cvt.rna.tf32.f32 %0, %1;" : "=r"(r) : "f"(f));
    return r;
}

__device__ __forceinline__ void mma_tf32(float* c, const uint32_t* a, const uint32_t* b) {
    asm volatile(
        "mma.sync.aligned.m16n8k8.row.col.f32.tf32.tf32.f32 "
        "{%0,%1,%2,%3}, {%4,%5,%6,%7}, {%8,%9}, {%0,%1,%2,%3};"
        : "+f"(c[0]), "+f"(c[1]), "+f"(c[2]), "+f"(c[3])
        : "r"(a[0]), "r"(a[1]), "r"(a[2]), "r"(a[3]), "r"(b[0]), "r"(b[1]));
}

__device__ __forceinline__ void cp_async16(uint32_t saddr, const void* gsrc, int src_bytes) {
    asm volatile("cp.async.cg.shared.global [%0], [%1], 16, %2;\n"
                 :: "r"(saddr), "l"(gsrc), "r"(src_bytes));
}

// ---------------------------------------------------------------------------
// Kernel 1: W fp32 -> tf32 bits (one-shot, ~4 us)
// ---------------------------------------------------------------------------
__global__ void __launch_bounds__(256) wconv_kernel(const float* __restrict__ wl,
                                                    const float* __restrict__ wr)
{
    int i = blockIdx.x * 256 + threadIdx.x;        // float4 units
    const bool isL = (i < 65536);
    int j = isL ? i : i - 65536;
    float4 v = reinterpret_cast<const float4*>(isL ? wl : wr)[j];
    uint4 o;
    o.x = f2tf32(v.x); o.y = f2tf32(v.y); o.z = f2tf32(v.z); o.w = f2tf32(v.w);
    reinterpret_cast<uint4*>(isL ? g_wl : g_wr)[j] = o;
}

// ---------------------------------------------------------------------------
// Shared GEMM tile body (BM=128 x BN=128, 8 warps of 32x64, BK=32).
// IS_X: A = x fp32 (in-reg CVT), B = g_wl.  else A = g_agg bits, B = g_wr.
// ---------------------------------------------------------------------------
template <bool IS_X>
__device__ __forceinline__ void gemm_compute_chunk(
    const uint32_t* as, float acc[2][8][4],
    int wm, int wn, int r8, int fc)
{
    const uint32_t* bs = as + A_WORDS;
    const float*    af = reinterpret_cast<const float*>(as);
#pragma unroll
    for (int ks = 0; ks < 4; ++ks) {
        const int kb = ks * 8;
        uint32_t afr[2][4];
#pragma unroll
        for (int mt = 0; mt < 2; ++mt) {
            const int r = wm * 32 + mt * 16 + r8;
            if (IS_X) {
                afr[mt][0] = f2tf32(af[r * SSTR + kb + fc]);
                afr[mt][1] = f2tf32(af[(r + 8) * SSTR + kb + fc]);
                afr[mt][2] = f2tf32(af[r * SSTR + kb + fc + 4]);
                afr[mt][3] = f2tf32(af[(r + 8) * SSTR + kb + fc + 4]);
            } else {
                afr[mt][0] = as[r * SSTR + kb + fc];
                afr[mt][1] = as[(r + 8) * SSTR + kb + fc];
                afr[mt][2] = as[r * SSTR + kb + fc + 4];
                afr[mt][3] = as[(r + 8) * SSTR + kb + fc + 4];
            }
        }
        uint32_t bfr[8][2];
#pragma unroll
        for (int nt = 0; nt < 8; ++nt) {
            const int o = wn * 64 + nt * 8 + r8;
            bfr[nt][0] = bs[o * SSTR + kb + fc];
            bfr[nt][1] = bs[o * SSTR + kb + fc + 4];
        }
#pragma unroll
        for (int mt = 0; mt < 2; ++mt)
#pragma unroll
            for (int nt = 0; nt < 8; ++nt)
                mma_tf32(acc[mt][nt], afr[mt], bfr[nt]);
    }
}

template <bool IS_X>
__device__ __forceinline__ void gemm_issue_chunk(
    uint32_t smem_u32, int stage, int ch,
    const float* x, int rowBase, int colBase, int Nrows, int tid)
{
    const uint32_t sA = smem_u32 + (stage * STG_WORDS) * 4;
    const uint32_t sB = sA + A_WORDS * 4;
    const int kk = ch * BK;
#pragma unroll
    for (int i = 0; i < 4; ++i) {                 // A: 128 x 32
        int idx = i * THREADS + tid;
        int r = idx >> 3, c4 = (idx & 7) * 4;
        int grow = rowBase + r;
        const void* g = IS_X
            ? (const void*)(x + (size_t)grow * C_DIM + kk + c4)
            : (const void*)(g_agg + (size_t)grow * C_DIM + kk + c4);
        cp_async16(sA + (r * SSTR + c4) * 4, g, (grow < Nrows) ? 16 : 0);
    }
    const uint32_t* Bp = IS_X ? g_wl : g_wr;
#pragma unroll
    for (int i = 0; i < 4; ++i) {                 // B: 128 x 32
        int idx = i * THREADS + tid;
        int o = idx >> 3, c4 = (idx & 7) * 4;
        cp_async16(sB + (o * SSTR + c4) * 4,
                   Bp + (size_t)(colBase + o) * C_DIM + kk + c4, 16);
    }
    asm volatile("cp.async.commit_group;\n");
}

// ---------------------------------------------------------------------------
// Kernel 2 (combo): mean blocks + interleaved x-GEMM CTAs in one grid.
//   bid mapping: every 16th bid (r==15, g<628) is x-GEMM CTA g;
//   the rest are mean blocks (2 nodes each).
// ---------------------------------------------------------------------------
__global__ void __launch_bounds__(THREADS, 2)
combo_kernel(const float* __restrict__ x,
             const float* __restrict__ nx,
             const float* __restrict__ bl,
             const float* __restrict__ br,
             float* __restrict__ out,
             int Nrows)
{
    const int bid = blockIdx.x;
    const int g   = bid >> 4;
    const int r   = bid & 15;
    const int tid = threadIdx.x;

    if (r == 15 && g < GEMM_CTAS) {
        // ==================== x-GEMM CTA ====================
        extern __shared__ uint32_t smem[];
        const uint32_t smem_u32 = (uint32_t)__cvta_generic_to_shared(smem);
        const int lane = tid & 31;
        const int warp = tid >> 5;
        const int wm   = warp & 3;
        const int wn   = warp >> 2;
        const int rowBase = (g >> 2) * BM;      // 0..156
        const int colBase = (g & 3) * BN;       // 0..3
        const int fc = lane & 3, r8 = lane >> 2;

        float acc[2][8][4];
#pragma unroll
        for (int mt = 0; mt < 2; ++mt)
#pragma unroll
            for (int nt = 0; nt < 8; ++nt)
#pragma unroll
                for (int i = 0; i < 4; ++i) acc[mt][nt][i] = 0.f;

        gemm_issue_chunk<true>(smem_u32, 0, 0, x, rowBase, colBase, Nrows, tid);
        for (int t = 0; t < NCH; ++t) {
            asm volatile("cp.async.wait_group 0;\n");
            __syncthreads();                      // chunk t visible; t-1 reads done
            if (t + 1 < NCH)
                gemm_issue_chunk<true>(smem_u32, (t + 1) & 1, t + 1,
                                       x, rowBase, colBase, Nrows, tid);
            gemm_compute_chunk<true>(smem + (t & 1) * STG_WORDS, acc, wm, wn, r8, fc);
        }

        // epilogue: out = acc + (bl+br)
#pragma unroll
        for (int nt = 0; nt < 8; ++nt) {
            const int col = colBase + wn * 64 + nt * 8 + 2 * (lane & 3);
            const float b0 = __ldg(bl + col)     + __ldg(br + col);
            const float b1 = __ldg(bl + col + 1) + __ldg(br + col + 1);
#pragma unroll
            for (int mt = 0; mt < 2; ++mt) {
                const int row0 = rowBase + wm * 32 + mt * 16 + r8;
                const int row1 = row0 + 8;
                if (row0 < Nrows) {
                    float2 v = make_float2(acc[mt][nt][0] + b0, acc[mt][nt][1] + b1);
                    *reinterpret_cast<float2*>(out + (size_t)row0 * OUT_DIM + col) = v;
                }
                if (row1 < Nrows) {
                    float2 v = make_float2(acc[mt][nt][2] + b0, acc[mt][nt][3] + b1);
                    *reinterpret_cast<float2*>(out + (size_t)row1 * OUT_DIM + col) = v;
                }
            }
        }
    } else {
        // ==================== mean block (2 nodes) ====================
        const int pair = bid - ((g < GEMM_CTAS) ? (g + (r == 15 ? 1 : 0)) : GEMM_CTAS);
        const int node = 2 * pair + (tid >> 7);
        const int c4   = tid & 127;
        if (node >= Nrows) return;
        const float4* p = reinterpret_cast<const float4*>(
                              nx + (size_t)node * K_NB * C_DIM) + c4;
        float4 sa = {0,0,0,0}, sb = {0,0,0,0};
#pragma unroll 8
        for (int k = 0; k < K_NB; k += 2) {      // two chains, deep MLP
            float4 va = p[(size_t)k * (C_DIM / 4)];
            float4 vb = p[(size_t)(k + 1) * (C_DIM / 4)];
            sa.x += va.x; sa.y += va.y; sa.z += va.z; sa.w += va.w;
            sb.x += vb.x; sb.y += vb.y; sb.z += vb.z; sb.w += vb.w;
        }
        const float inv = 1.0f / (float)K_NB;
        uint4 o;
        o.x = f2tf32((sa.x + sb.x) * inv); o.y = f2tf32((sa.y + sb.y) * inv);
        o.z = f2tf32((sa.z + sb.z) * inv); o.w = f2tf32((sa.w + sb.w) * inv);
        reinterpret_cast<uint4*>(g_agg + (size_t)node * C_DIM)[c4] = o;
    }
}

// ---------------------------------------------------------------------------
// Kernel 3: out += agg @ Wr^T   (3-stage pipeline, single barrier per chunk)
// ---------------------------------------------------------------------------
__global__ void __launch_bounds__(THREADS, 2)
agg_gemm_kernel(float* __restrict__ out, int Nrows)
{
    extern __shared__ uint32_t smem[];
    const uint32_t smem_u32 = (uint32_t)__cvta_generic_to_shared(smem);
    const int tid  = threadIdx.x;
    const int lane = tid & 31;
    const int warp = tid >> 5;
    const int wm   = warp & 3;
    const int wn   = warp >> 2;
    const int rowBase = blockIdx.y * BM;
    const int colBase = blockIdx.x * BN;
    const int fc = lane & 3, r8 = lane >> 2;

    float acc[2][8][4];
#pragma unroll
    for (int mt = 0; mt < 2; ++mt)
#pragma unroll
        for (int nt = 0; nt < 8; ++nt)
#pragma unroll
            for (int i = 0; i < 4; ++i) acc[mt][nt][i] = 0.f;

    gemm_issue_chunk<false>(smem_u32, 0, 0, nullptr, rowBase, colBase, Nrows, tid);
    gemm_issue_chunk<false>(smem_u32, 1, 1, nullptr, rowBase, colBase, Nrows, tid);
    for (int t = 0; t < NCH; ++t) {
        if (t < NCH - 1) asm volatile("cp.async.wait_group 1;\n");
        else             asm volatile("cp.async.wait_group 0;\n");
        __syncthreads();                  // chunk t visible; all warps done t-1
        if (t + 2 < NCH)
            gemm_issue_chunk<false>(smem_u32, (t + 2) % 3, t + 2,
                                    nullptr, rowBase, colBase, Nrows, tid);
        gemm_compute_chunk<false>(smem + (t % 3) * STG_WORDS, acc, wm, wn, r8, fc);
    }

    // epilogue: out += acc   (x-GEMM already wrote x@Wl + bias)
#pragma unroll
    for (int nt = 0; nt < 8; ++nt) {
        const int col = colBase + wn * 64 + nt * 8 + 2 * (lane & 3);
#pragma unroll
        for (int mt = 0; mt < 2; ++mt) {
            const int row0 = rowBase + wm * 32 + mt * 16 + r8;
            const int row1 = row0 + 8;
            if (row0 < Nrows) {
                float2* p = reinterpret_cast<float2*>(out + (size_t)row0 * OUT_DIM + col);
                float2 v = *p;
                v.x += acc[mt][nt][0]; v.y += acc[mt][nt][1];
                *p = v;
            }
            if (row1 < Nrows) {
                float2* p = reinterpret_cast<float2*>(out + (size_t)row1 * OUT_DIM + col);
                float2 v = *p;
                v.x += acc[mt][nt][2]; v.y += acc[mt][nt][3];
                *p = v;
            }
        }
    }
}

// ---------------------------------------------------------------------------
// Launch
// ---------------------------------------------------------------------------
extern "C" void kernel_launch(void* const* d_in, const int* in_sizes, int n_in,
                              void* d_out, int out_size)
{
    const float* x     = (const float*)d_in[0];
    const float* neigh = (const float*)d_in[1];
    const float* Wl    = (const float*)d_in[2];
    const float* bl    = (const float*)d_in[3];
    const float* Wr    = (const float*)d_in[4];
    const float* br    = (const float*)d_in[5];
    float* out = (float*)d_out;

    const int N = in_sizes[0] / C_DIM;        // 20000

    wconv_kernel<<<512, 256>>>(Wl, Wr);

    static int smem_set = 0;
    if (!smem_set) {
        cudaFuncSetAttribute(combo_kernel,    cudaFuncAttributeMaxDynamicSharedMemorySize, SMEM_COMBO);
        cudaFuncSetAttribute(agg_gemm_kernel, cudaFuncAttributeMaxDynamicSharedMemorySize, SMEM_AGG);
        smem_set = 1;
    }

    // combo: 10000 mean pair-blocks + 628 x-GEMM CTAs, interleaved every 16th bid
    const int combo_grid = (N / 2) + GEMM_CTAS;     // 10628
    combo_kernel<<<combo_grid, THREADS, SMEM_COMBO>>>(x, neigh, bl, br, out, N);

    dim3 grid2(OUT_DIM / BN, (N + BM - 1) / BM);    // (4, 157)
    agg_gemm_kernel<<<grid2, THREADS, SMEM_AGG>>>(out, N);
}

// round 11
// speedup vs baseline: 1.8912x; 1.1030x over previous
#include <cuda_runtime.h>
#include <cstdint>

// Shape-fixed problem: N=20000, K=32, C=512, OUT=512
#define C_DIM   512
#define OUT_DIM 512
#define K_NB    32
#define N_MAX   20000

#define BM       128
#define BN       128
#define BK       32
#define SSTR     36                        // padded smem row stride (words)
#define THREADS  256
#define A_WORDS  (BM * SSTR)               // 4608
#define B_WORDS  (BN * SSTR)               // 4608
#define STG_WORDS (A_WORDS + B_WORDS)      // 9216
#define SMEM_BYTES (2 * STG_WORDS * 4)     // 73728 (2-stage)

#define NRB       157                      // row-blocks of 128
#define GEMM_CTAS 628                      // 4 cols x 157 row-blocks
#define GDELAY    16                       // gemm slot delay (groups)

// tf32-bit scratch + readiness counters
__device__ uint32_t g_agg[(size_t)N_MAX * C_DIM];
__device__ uint32_t g_wl [OUT_DIM * C_DIM];
__device__ uint32_t g_wr [OUT_DIM * C_DIM];
__device__ int      g_cnt[NRB];

__device__ __forceinline__ uint32_t f2tf32(float f) {
    uint32_t r;
    asm("cvt.rna.tf32.f32 %0, %1;" : "=r"(r) : "f"(f));
    return r;
}

__device__ __forceinline__ void mma_tf32(float* c, const uint32_t* a, const uint32_t* b) {
    asm volatile(
        "mma.sync.aligned.m16n8k8.row.col.f32.tf32.tf32.f32 "
        "{%0,%1,%2,%3}, {%4,%5,%6,%7}, {%8,%9}, {%0,%1,%2,%3};"
        : "+f"(c[0]), "+f"(c[1]), "+f"(c[2]), "+f"(c[3])
        : "r"(a[0]), "r"(a[1]), "r"(a[2]), "r"(a[3]), "r"(b[0]), "r"(b[1]));
}

__device__ __forceinline__ void cp_async16(uint32_t saddr, const void* gsrc, int src_bytes) {
    asm volatile("cp.async.cg.shared.global [%0], [%1], 16, %2;\n"
                 :: "r"(saddr), "l"(gsrc), "r"(src_bytes));
}

// ---------------------------------------------------------------------------
// Kernel 1: W fp32 -> tf32 bits + zero readiness counters (each replay)
// ---------------------------------------------------------------------------
__global__ void __launch_bounds__(256) wconv_kernel(const float* __restrict__ wl,
                                                    const float* __restrict__ wr)
{
    int i = blockIdx.x * 256 + threadIdx.x;        // float4 units
    if (i < NRB) g_cnt[i] = 0;
    const bool isL = (i < 65536);
    int j = isL ? i : i - 65536;
    float4 v = reinterpret_cast<const float4*>(isL ? wl : wr)[j];
    uint4 o;
    o.x = f2tf32(v.x); o.y = f2tf32(v.y); o.z = f2tf32(v.z); o.w = f2tf32(v.w);
    reinterpret_cast<uint4*>(isL ? g_wl : g_wr)[j] = o;
}

// ---------------------------------------------------------------------------
// GEMM tile helpers (128x128, 8 warps of 32x64)
// ---------------------------------------------------------------------------
template <bool IS_X>
__device__ __forceinline__ void gemm_compute_chunk(
    const uint32_t* as, float acc[2][8][4], int wm, int wn, int r8, int fc)
{
    const uint32_t* bs = as + A_WORDS;
    const float*    af = reinterpret_cast<const float*>(as);
#pragma unroll
    for (int ks = 0; ks < 4; ++ks) {
        const int kb = ks * 8;
        uint32_t afr[2][4];
#pragma unroll
        for (int mt = 0; mt < 2; ++mt) {
            const int r = wm * 32 + mt * 16 + r8;
            if (IS_X) {
                afr[mt][0] = f2tf32(af[r * SSTR + kb + fc]);
                afr[mt][1] = f2tf32(af[(r + 8) * SSTR + kb + fc]);
                afr[mt][2] = f2tf32(af[r * SSTR + kb + fc + 4]);
                afr[mt][3] = f2tf32(af[(r + 8) * SSTR + kb + fc + 4]);
            } else {
                afr[mt][0] = as[r * SSTR + kb + fc];
                afr[mt][1] = as[(r + 8) * SSTR + kb + fc];
                afr[mt][2] = as[r * SSTR + kb + fc + 4];
                afr[mt][3] = as[(r + 8) * SSTR + kb + fc + 4];
            }
        }
        uint32_t bfr[8][2];
#pragma unroll
        for (int nt = 0; nt < 8; ++nt) {
            const int o = wn * 64 + nt * 8 + r8;
            bfr[nt][0] = bs[o * SSTR + kb + fc];
            bfr[nt][1] = bs[o * SSTR + kb + fc + 4];
        }
#pragma unroll
        for (int mt = 0; mt < 2; ++mt)
#pragma unroll
            for (int nt = 0; nt < 8; ++nt)
                mma_tf32(acc[mt][nt], afr[mt], bfr[nt]);
    }
}

// ch in [0,32): 0-15 = x/Wl, 16-31 = agg/Wr
__device__ __forceinline__ void gemm_issue_chunk(
    uint32_t smem_u32, int stage, int ch,
    const float* x, int rowBase, int colBase, int Nrows, int tid)
{
    const uint32_t sA = smem_u32 + (stage * STG_WORDS) * 4;
    const uint32_t sB = sA + A_WORDS * 4;
    const bool is_x = (ch < 16);
    const int kk = (ch & 15) * BK;
#pragma unroll
    for (int i = 0; i < 4; ++i) {                 // A: 128 x 32
        int idx = i * THREADS + tid;
        int r = idx >> 3, c4 = (idx & 7) * 4;
        int grow = rowBase + r;
        const void* g = is_x
            ? (const void*)(x + (size_t)grow * C_DIM + kk + c4)
            : (const void*)(g_agg + (size_t)grow * C_DIM + kk + c4);
        cp_async16(sA + (r * SSTR + c4) * 4, g, (grow < Nrows) ? 16 : 0);
    }
    const uint32_t* Bp = is_x ? g_wl : g_wr;
#pragma unroll
    for (int i = 0; i < 4; ++i) {                 // B: 128 x 32
        int idx = i * THREADS + tid;
        int o = idx >> 3, c4 = (idx & 7) * 4;
        cp_async16(sB + (o * SSTR + c4) * 4,
                   Bp + (size_t)(colBase + o) * C_DIM + kk + c4, 16);
    }
    asm volatile("cp.async.commit_group;\n");
}

// ---------------------------------------------------------------------------
// Combo kernel: 16-bid groups = 15 mean pair-blocks + 1 full-K GEMM CTA.
// GEMM CTA: chunks 0-15 x/Wl (no deps), spin on g_cnt[rb], chunks 16-31 agg/Wr.
// ---------------------------------------------------------------------------
__global__ void __launch_bounds__(THREADS, 2)
combo_kernel(const float* __restrict__ x,
             const float* __restrict__ nx,
             const float* __restrict__ bl,
             const float* __restrict__ br,
             float* __restrict__ out,
             int Nrows)
{
    const int bid = blockIdx.x;
    const int g16 = bid >> 4;
    const int r   = bid & 15;
    const int tid = threadIdx.x;

    if (r == 15) {
        // ==================== GEMM CTA (full K=1024) ====================
        const int gd = g16 - GDELAY;
        if (gd < 0 || gd >= GEMM_CTAS) return;

        extern __shared__ uint32_t smem[];
        const uint32_t smem_u32 = (uint32_t)__cvta_generic_to_shared(smem);
        const int lane = tid & 31;
        const int warp = tid >> 5;
        const int wm   = warp & 3;
        const int wn   = warp >> 2;
        const int rb      = gd >> 2;
        const int rowBase = rb * BM;
        const int colBase = (gd & 3) * BN;
        const int fc = lane & 3, r8 = lane >> 2;

        float acc[2][8][4];
#pragma unroll
        for (int mt = 0; mt < 2; ++mt)
#pragma unroll
            for (int nt = 0; nt < 8; ++nt)
#pragma unroll
                for (int i = 0; i < 4; ++i) acc[mt][nt][i] = 0.f;

        gemm_issue_chunk(smem_u32, 0, 0, x, rowBase, colBase, Nrows, tid);
        for (int t = 0; t < 32; ++t) {
            asm volatile("cp.async.wait_group 0;\n");
            __syncthreads();                      // chunk t visible; t-1 reads done
            if (t + 1 < 32) {
                if (t + 1 == 16) {
                    // dependency: agg rows of this row-block must be written
                    if (tid == 0) {
                        const int pairs  = (Nrows + 1) >> 1;
                        const int target = min(64, pairs - rb * 64);
                        int c;
                        do {
                            asm volatile("ld.acquire.gpu.global.s32 %0, [%1];"
                                         : "=r"(c) : "l"(g_cnt + rb) : "memory");
                        } while (c < target);
                    }
                    __syncthreads();
                }
                gemm_issue_chunk(smem_u32, (t + 1) & 1, t + 1,
                                 x, rowBase, colBase, Nrows, tid);
            }
            if (t < 16) gemm_compute_chunk<true >(smem + (t & 1) * STG_WORDS, acc, wm, wn, r8, fc);
            else        gemm_compute_chunk<false>(smem + (t & 1) * STG_WORDS, acc, wm, wn, r8, fc);
        }

        // epilogue: out = acc + (bl+br), single write
#pragma unroll
        for (int nt = 0; nt < 8; ++nt) {
            const int col = colBase + wn * 64 + nt * 8 + 2 * (lane & 3);
            const float b0 = __ldg(bl + col)     + __ldg(br + col);
            const float b1 = __ldg(bl + col + 1) + __ldg(br + col + 1);
#pragma unroll
            for (int mt = 0; mt < 2; ++mt) {
                const int row0 = rowBase + wm * 32 + mt * 16 + r8;
                const int row1 = row0 + 8;
                if (row0 < Nrows) {
                    float2 v = make_float2(acc[mt][nt][0] + b0, acc[mt][nt][1] + b1);
                    *reinterpret_cast<float2*>(out + (size_t)row0 * OUT_DIM + col) = v;
                }
                if (row1 < Nrows) {
                    float2 v = make_float2(acc[mt][nt][2] + b0, acc[mt][nt][3] + b1);
                    *reinterpret_cast<float2*>(out + (size_t)row1 * OUT_DIM + col) = v;
                }
            }
        }
    } else {
        // ==================== mean pair-block (2 nodes) ====================
        const int pair = g16 * 15 + r;
        if (pair * 2 >= Nrows) return;
        const int node = 2 * pair + (tid >> 7);
        const int c4   = tid & 127;
        if (node < Nrows) {
            const float4* p = reinterpret_cast<const float4*>(
                                  nx + (size_t)node * K_NB * C_DIM) + c4;
            float4 sa = {0,0,0,0}, sb = {0,0,0,0};
#pragma unroll 8
            for (int k = 0; k < K_NB; k += 2) {
                float4 va = p[(size_t)k * (C_DIM / 4)];
                float4 vb = p[(size_t)(k + 1) * (C_DIM / 4)];
                sa.x += va.x; sa.y += va.y; sa.z += va.z; sa.w += va.w;
                sb.x += vb.x; sb.y += vb.y; sb.z += vb.z; sb.w += vb.w;
            }
            const float inv = 1.0f / (float)K_NB;
            uint4 o;
            o.x = f2tf32((sa.x + sb.x) * inv); o.y = f2tf32((sa.y + sb.y) * inv);
            o.z = f2tf32((sa.z + sb.z) * inv); o.w = f2tf32((sa.w + sb.w) * inv);
            reinterpret_cast<uint4*>(g_agg + (size_t)node * C_DIM)[c4] = o;
        }
        __syncthreads();                      // both nodes' stores complete
        if (tid == 0) {
            __threadfence();                  // publish g_agg before counting
            atomicAdd(g_cnt + (pair >> 6), 1);
        }
    }
}

// ---------------------------------------------------------------------------
// Launch
// ---------------------------------------------------------------------------
extern "C" void kernel_launch(void* const* d_in, const int* in_sizes, int n_in,
                              void* d_out, int out_size)
{
    const float* x     = (const float*)d_in[0];
    const float* neigh = (const float*)d_in[1];
    const float* Wl    = (const float*)d_in[2];
    const float* bl    = (const float*)d_in[3];
    const float* Wr    = (const float*)d_in[4];
    const float* br    = (const float*)d_in[5];
    float* out = (float*)d_out;

    const int N = in_sizes[0] / C_DIM;        // 20000

    wconv_kernel<<<512, 256>>>(Wl, Wr);       // also zeroes g_cnt

    static int smem_set = 0;
    if (!smem_set) {
        cudaFuncSetAttribute(combo_kernel, cudaFuncAttributeMaxDynamicSharedMemorySize, SMEM_BYTES);
        smem_set = 1;
    }

    // groups: mean needs ceil((N/2)/15)=667; gemm needs 628+GDELAY=644
    const int pairs  = (N + 1) / 2;
    const int groups_mean = (pairs + 14) / 15;
    const int groups_gemm = GEMM_CTAS + GDELAY;
    const int groups = (groups_mean > groups_gemm) ? groups_mean : groups_gemm;
    combo_kernel<<<groups * 16, THREADS, SMEM_BYTES>>>(x, neigh, bl, br, out, N);
}

// round 13
// speedup vs baseline: 1.9525x; 1.0324x over previous
#include <cuda_runtime.h>
#include <cstdint>

// Shape-fixed problem: N=20000, K=32, C=512, OUT=512
#define C_DIM   512
#define OUT_DIM 512
#define K_NB    32
#define N_MAX   20000

#define BM       64
#define BN       128
#define BK       32
#define SSTR     36                        // padded smem row stride (words)
#define THREADS  256
#define A_WORDS  (BM * SSTR)               // 2304
#define B_WORDS  (BN * SSTR)               // 4608
#define STG_WORDS (A_WORDS + B_WORDS)      // 6912
#define SMEM_BYTES (2 * STG_WORDS * 4)     // 55296 (2-stage) -> 3 blocks/SM

#define NRB       313                      // row-blocks of 64
#define GEMM_CTAS (NRB * 4)                // 1252
#define GDELAY    16                       // gemm slot delay (groups)

// tf32-bit scratch + readiness counters
__device__ uint32_t g_agg[(size_t)N_MAX * C_DIM];
__device__ uint32_t g_wl [OUT_DIM * C_DIM];
__device__ uint32_t g_wr [OUT_DIM * C_DIM];
__device__ int      g_cnt[NRB];

__device__ __forceinline__ uint32_t f2tf32(float f) {
    uint32_t r;
    asm("cvt.rna.tf32.f32 %0, %1;" : "=r"(r) : "f"(f));
    return r;
}

__device__ __forceinline__ void mma_tf32(float* c, const uint32_t* a, const uint32_t* b) {
    asm volatile(
        "mma.sync.aligned.m16n8k8.row.col.f32.tf32.tf32.f32 "
        "{%0,%1,%2,%3}, {%4,%5,%6,%7}, {%8,%9}, {%0,%1,%2,%3};"
        : "+f"(c[0]), "+f"(c[1]), "+f"(c[2]), "+f"(c[3])
        : "r"(a[0]), "r"(a[1]), "r"(a[2]), "r"(a[3]), "r"(b[0]), "r"(b[1]));
}

__device__ __forceinline__ void cp_async16(uint32_t saddr, const void* gsrc, int src_bytes) {
    asm volatile("cp.async.cg.shared.global [%0], [%1], 16, %2;\n"
                 :: "r"(saddr), "l"(gsrc), "r"(src_bytes));
}

// ---------------------------------------------------------------------------
// Kernel 1: W fp32 -> tf32 bits + zero readiness counters (each replay)
// ---------------------------------------------------------------------------
__global__ void __launch_bounds__(256) wconv_kernel(const float* __restrict__ wl,
                                                    const float* __restrict__ wr)
{
    int i = blockIdx.x * 256 + threadIdx.x;        // float4 units
    if (i < NRB) g_cnt[i] = 0;
    const bool isL = (i < 65536);
    int j = isL ? i : i - 65536;
    float4 v = reinterpret_cast<const float4*>(isL ? wl : wr)[j];
    uint4 o;
    o.x = f2tf32(v.x); o.y = f2tf32(v.y); o.z = f2tf32(v.z); o.w = f2tf32(v.w);
    reinterpret_cast<uint4*>(isL ? g_wl : g_wr)[j] = o;
}

// ---------------------------------------------------------------------------
// GEMM tile helpers (64x128 block, 8 warps of 32x32)
//   wm = warp & 1 (row group of 32), wn = warp >> 1 (col group of 32)
// ---------------------------------------------------------------------------
template <bool IS_X>
__device__ __forceinline__ void gemm_compute_chunk(
    const uint32_t* as, float acc[2][4][4], int wm, int wn, int r8, int fc)
{
    const uint32_t* bs = as + A_WORDS;
    const float*    af = reinterpret_cast<const float*>(as);
#pragma unroll
    for (int ks = 0; ks < 4; ++ks) {
        const int kb = ks * 8;
        uint32_t afr[2][4];
#pragma unroll
        for (int mt = 0; mt < 2; ++mt) {
            const int r = wm * 32 + mt * 16 + r8;
            if (IS_X) {
                afr[mt][0] = f2tf32(af[r * SSTR + kb + fc]);
                afr[mt][1] = f2tf32(af[(r + 8) * SSTR + kb + fc]);
                afr[mt][2] = f2tf32(af[r * SSTR + kb + fc + 4]);
                afr[mt][3] = f2tf32(af[(r + 8) * SSTR + kb + fc + 4]);
            } else {
                afr[mt][0] = as[r * SSTR + kb + fc];
                afr[mt][1] = as[(r + 8) * SSTR + kb + fc];
                afr[mt][2] = as[r * SSTR + kb + fc + 4];
                afr[mt][3] = as[(r + 8) * SSTR + kb + fc + 4];
            }
        }
        uint32_t bfr[4][2];
#pragma unroll
        for (int nt = 0; nt < 4; ++nt) {
            const int o = wn * 32 + nt * 8 + r8;
            bfr[nt][0] = bs[o * SSTR + kb + fc];
            bfr[nt][1] = bs[o * SSTR + kb + fc + 4];
        }
#pragma unroll
        for (int mt = 0; mt < 2; ++mt)
#pragma unroll
            for (int nt = 0; nt < 4; ++nt)
                mma_tf32(acc[mt][nt], afr[mt], bfr[nt]);
    }
}

// ch in [0,32): 0-15 = x/Wl, 16-31 = agg/Wr
__device__ __forceinline__ void gemm_issue_chunk(
    uint32_t smem_u32, int stage, int ch,
    const float* x, int rowBase, int colBase, int Nrows, int tid)
{
    const uint32_t sA = smem_u32 + (stage * STG_WORDS) * 4;
    const uint32_t sB = sA + A_WORDS * 4;
    const bool is_x = (ch < 16);
    const int kk = (ch & 15) * BK;
#pragma unroll
    for (int i = 0; i < 2; ++i) {                 // A: 64 x 32
        int idx = i * THREADS + tid;              // 0..511
        int r = idx >> 3, c4 = (idx & 7) * 4;
        int grow = rowBase + r;
        const void* g = is_x
            ? (const void*)(x + (size_t)grow * C_DIM + kk + c4)
            : (const void*)(g_agg + (size_t)grow * C_DIM + kk + c4);
        cp_async16(sA + (r * SSTR + c4) * 4, g, (grow < Nrows) ? 16 : 0);
    }
    const uint32_t* Bp = is_x ? g_wl : g_wr;
#pragma unroll
    for (int i = 0; i < 4; ++i) {                 // B: 128 x 32
        int idx = i * THREADS + tid;              // 0..1023
        int o = idx >> 3, c4 = (idx & 7) * 4;
        cp_async16(sB + (o * SSTR + c4) * 4,
                   Bp + (size_t)(colBase + o) * C_DIM + kk + c4, 16);
    }
    asm volatile("cp.async.commit_group;\n");
}

// ---------------------------------------------------------------------------
// Combo kernel: 16-bid groups = 14 mean pair-blocks + 2 full-K GEMM CTAs.
// GEMM CTA: chunks 0-15 x/Wl (no deps), spin on g_cnt[rb], chunks 16-31 agg/Wr.
// ---------------------------------------------------------------------------
__global__ void __launch_bounds__(THREADS, 3)
combo_kernel(const float* __restrict__ x,
             const float* __restrict__ nx,
             const float* __restrict__ bl,
             const float* __restrict__ br,
             float* __restrict__ out,
             int Nrows)
{
    const int bid = blockIdx.x;
    const int g16 = bid >> 4;
    const int r   = bid & 15;
    const int tid = threadIdx.x;

    if (r >= 14) {
        // ==================== GEMM CTA (full K=1024) ====================
        const int gd = (g16 - GDELAY) * 2 + (r - 14);
        if (gd < 0 || gd >= GEMM_CTAS) return;

        extern __shared__ uint32_t smem[];
        const uint32_t smem_u32 = (uint32_t)__cvta_generic_to_shared(smem);
        const int lane = tid & 31;
        const int warp = tid >> 5;
        const int wm   = warp & 1;
        const int wn   = warp >> 1;
        const int rb      = gd >> 2;
        const int rowBase = rb * BM;
        const int colBase = (gd & 3) * BN;
        const int fc = lane & 3, r8 = lane >> 2;

        float acc[2][4][4];
#pragma unroll
        for (int mt = 0; mt < 2; ++mt)
#pragma unroll
            for (int nt = 0; nt < 4; ++nt)
#pragma unroll
                for (int i = 0; i < 4; ++i) acc[mt][nt][i] = 0.f;

        gemm_issue_chunk(smem_u32, 0, 0, x, rowBase, colBase, Nrows, tid);
        for (int t = 0; t < 32; ++t) {
            asm volatile("cp.async.wait_group 0;\n");
            __syncthreads();                      // chunk t visible; t-1 reads done
            if (t + 1 < 32) {
                if (t + 1 == 16) {
                    // dependency: agg rows of this 64-row block must be written
                    if (tid == 0) {
                        const int pairs  = (Nrows + 1) >> 1;
                        const int target = min(32, pairs - rb * 32);
                        int c;
                        do {
                            asm volatile("ld.acquire.gpu.global.s32 %0, [%1];"
                                         : "=r"(c) : "l"(g_cnt + rb) : "memory");
                        } while (c < target);
                    }
                    __syncthreads();
                }
                gemm_issue_chunk(smem_u32, (t + 1) & 1, t + 1,
                                 x, rowBase, colBase, Nrows, tid);
            }
            if (t < 16) gemm_compute_chunk<true >(smem + (t & 1) * STG_WORDS, acc, wm, wn, r8, fc);
            else        gemm_compute_chunk<false>(smem + (t & 1) * STG_WORDS, acc, wm, wn, r8, fc);
        }

        // epilogue: out = acc + (bl+br), single write
#pragma unroll
        for (int nt = 0; nt < 4; ++nt) {
            const int col = colBase + wn * 32 + nt * 8 + 2 * (lane & 3);
            const float b0 = __ldg(bl + col)     + __ldg(br + col);
            const float b1 = __ldg(bl + col + 1) + __ldg(br + col + 1);
#pragma unroll
            for (int mt = 0; mt < 2; ++mt) {
                const int row0 = rowBase + wm * 32 + mt * 16 + r8;
                const int row1 = row0 + 8;
                if (row0 < Nrows) {
                    float2 v = make_float2(acc[mt][nt][0] + b0, acc[mt][nt][1] + b1);
                    *reinterpret_cast<float2*>(out + (size_t)row0 * OUT_DIM + col) = v;
                }
                if (row1 < Nrows) {
                    float2 v = make_float2(acc[mt][nt][2] + b0, acc[mt][nt][3] + b1);
                    *reinterpret_cast<float2*>(out + (size_t)row1 * OUT_DIM + col) = v;
                }
            }
        }
    } else {
        // ==================== mean pair-block (2 nodes) ====================
        const int pair = g16 * 14 + r;
        if (pair * 2 >= Nrows) return;
        const int node = 2 * pair + (tid >> 7);
        const int c4   = tid & 127;
        if (node < Nrows) {
            const float4* p = reinterpret_cast<const float4*>(
                                  nx + (size_t)node * K_NB * C_DIM) + c4;
            float4 s0 = {0,0,0,0}, s1 = {0,0,0,0}, s2 = {0,0,0,0}, s3 = {0,0,0,0};
#pragma unroll 4
            for (int k = 0; k < K_NB; k += 4) {   // 4 independent chains, deep MLP
                float4 v0 = p[(size_t)k * (C_DIM / 4)];
                float4 v1 = p[(size_t)(k + 1) * (C_DIM / 4)];
                float4 v2 = p[(size_t)(k + 2) * (C_DIM / 4)];
                float4 v3 = p[(size_t)(k + 3) * (C_DIM / 4)];
                s0.x += v0.x; s0.y += v0.y; s0.z += v0.z; s0.w += v0.w;
                s1.x += v1.x; s1.y += v1.y; s1.z += v1.z; s1.w += v1.w;
                s2.x += v2.x; s2.y += v2.y; s2.z += v2.z; s2.w += v2.w;
                s3.x += v3.x; s3.y += v3.y; s3.z += v3.z; s3.w += v3.w;
            }
            const float inv = 1.0f / (float)K_NB;
            uint4 o;
            o.x = f2tf32((s0.x + s1.x + s2.x + s3.x) * inv);
            o.y = f2tf32((s0.y + s1.y + s2.y + s3.y) * inv);
            o.z = f2tf32((s0.z + s1.z + s2.z + s3.z) * inv);
            o.w = f2tf32((s0.w + s1.w + s2.w + s3.w) * inv);
            reinterpret_cast<uint4*>(g_agg + (size_t)node * C_DIM)[c4] = o;
        }
        __syncthreads();                      // both nodes' stores complete
        if (tid == 0) {
            __threadfence();                  // publish g_agg before counting
            atomicAdd(g_cnt + (pair >> 5), 1);
        }
    }
}

// ---------------------------------------------------------------------------
// Launch
// ---------------------------------------------------------------------------
extern "C" void kernel_launch(void* const* d_in, const int* in_sizes, int n_in,
                              void* d_out, int out_size)
{
    const float* x     = (const float*)d_in[0];
    const float* neigh = (const float*)d_in[1];
    const float* Wl    = (const float*)d_in[2];
    const float* bl    = (const float*)d_in[3];
    const float* Wr    = (const float*)d_in[4];
    const float* br    = (const float*)d_in[5];
    float* out = (float*)d_out;

    const int N = in_sizes[0] / C_DIM;        // 20000

    wconv_kernel<<<512, 256>>>(Wl, Wr);       // also zeroes g_cnt

    static int smem_set = 0;
    if (!smem_set) {
        cudaFuncSetAttribute(combo_kernel, cudaFuncAttributeMaxDynamicSharedMemorySize, SMEM_BYTES);
        smem_set = 1;
    }

    // groups: mean needs ceil((N/2)/14)=715; gemm needs 1252/2+16=642
    const int pairs  = (N + 1) / 2;
    const int groups_mean = (pairs + 13) / 14;
    const int groups_gemm = GEMM_CTAS / 2 + GDELAY;
    const int groups = (groups_mean > groups_gemm) ? groups_mean : groups_gemm;
    combo_kernel<<<groups * 16, THREADS, SMEM_BYTES>>>(x, neigh, bl, br, out, N);
}

// round 15
// speedup vs baseline: 1.9813x; 1.0148x over previous
#include <cuda_runtime.h>
#include <cstdint>

// Shape-fixed problem: N=20000, K=32, C=512, OUT=512
#define C_DIM   512
#define OUT_DIM 512
#define K_NB    32
#define N_MAX   20000

#define BM       64
#define BN       128
#define BK       32
#define SSTR     36                        // padded smem row stride (words)
#define THREADS  256
#define A_WORDS  (BM * SSTR)               // 2304
#define B_WORDS  (BN * SSTR)               // 4608
#define STG_WORDS (A_WORDS + B_WORDS)      // 6912
#define SMEM_BYTES (2 * STG_WORDS * 4)     // 55296 (2-stage) -> 3 blocks/SM

#define NRB       313                      // row-blocks of 64
#define GEMM_CTAS (NRB * 4)                // 1252
#define GDELAY    16                       // gemm slot delay (groups)

// tf32-bit scratch + readiness counters
__device__ uint32_t g_agg[(size_t)N_MAX * C_DIM];
__device__ uint32_t g_wl [OUT_DIM * C_DIM];
__device__ uint32_t g_wr [OUT_DIM * C_DIM];
__device__ int      g_cnt[NRB];

__device__ __forceinline__ uint32_t f2tf32(float f) {
    uint32_t r;
    asm("cvt.rna.tf32.f32 %0, %1;" : "=r"(r) : "f"(f));
    return r;
}

// streaming read via cache-hint policy (evict_first): read-once data
__device__ __forceinline__ uint64_t mk_evict_first_policy() {
    uint64_t pol;
    asm("createpolicy.fractional.L2::evict_first.b64 %0, 1.0;" : "=l"(pol));
    return pol;
}
__device__ __forceinline__ float4 ldg_stream(const float4* p, uint64_t pol) {
    float4 v;
    asm("ld.global.nc.L2::cache_hint.v4.f32 {%0,%1,%2,%3}, [%4], %5;"
        : "=f"(v.x), "=f"(v.y), "=f"(v.z), "=f"(v.w) : "l"(p), "l"(pol));
    return v;
}

// streaming write: output has no reuse
__device__ __forceinline__ void stg_cs(float* p, float2 v) {
    asm volatile("st.global.cs.v2.f32 [%0], {%1,%2};" :: "l"(p), "f"(v.x), "f"(v.y) : "memory");
}

__device__ __forceinline__ void mma_tf32(float* c, const uint32_t* a, const uint32_t* b) {
    asm volatile(
        "mma.sync.aligned.m16n8k8.row.col.f32.tf32.tf32.f32 "
        "{%0,%1,%2,%3}, {%4,%5,%6,%7}, {%8,%9}, {%0,%1,%2,%3};"
        : "+f"(c[0]), "+f"(c[1]), "+f"(c[2]), "+f"(c[3])
        : "r"(a[0]), "r"(a[1]), "r"(a[2]), "r"(a[3]), "r"(b[0]), "r"(b[1]));
}

__device__ __forceinline__ void cp_async16(uint32_t saddr, const void* gsrc, int src_bytes) {
    asm volatile("cp.async.cg.shared.global [%0], [%1], 16, %2;\n"
                 :: "r"(saddr), "l"(gsrc), "r"(src_bytes));
}

// ---------------------------------------------------------------------------
// Kernel 1: W fp32 -> tf32 bits + zero readiness counters (each replay)
// ---------------------------------------------------------------------------
__global__ void __launch_bounds__(256) wconv_kernel(const float* __restrict__ wl,
                                                    const float* __restrict__ wr)
{
    int i = blockIdx.x * 256 + threadIdx.x;        // float4 units
    if (i < NRB) g_cnt[i] = 0;
    const bool isL = (i < 65536);
    int j = isL ? i : i - 65536;
    float4 v = reinterpret_cast<const float4*>(isL ? wl : wr)[j];
    uint4 o;
    o.x = f2tf32(v.x); o.y = f2tf32(v.y); o.z = f2tf32(v.z); o.w = f2tf32(v.w);
    reinterpret_cast<uint4*>(isL ? g_wl : g_wr)[j] = o;
}

// ---------------------------------------------------------------------------
// GEMM tile helpers (64x128 block, 8 warps of 32x32)
// ---------------------------------------------------------------------------
template <bool IS_X>
__device__ __forceinline__ void gemm_compute_chunk(
    const uint32_t* as, float acc[2][4][4], int wm, int wn, int r8, int fc)
{
    const uint32_t* bs = as + A_WORDS;
    const float*    af = reinterpret_cast<const float*>(as);
#pragma unroll
    for (int ks = 0; ks < 4; ++ks) {
        const int kb = ks * 8;
        uint32_t afr[2][4];
#pragma unroll
        for (int mt = 0; mt < 2; ++mt) {
            const int r = wm * 32 + mt * 16 + r8;
            if (IS_X) {
                afr[mt][0] = f2tf32(af[r * SSTR + kb + fc]);
                afr[mt][1] = f2tf32(af[(r + 8) * SSTR + kb + fc]);
                afr[mt][2] = f2tf32(af[r * SSTR + kb + fc + 4]);
                afr[mt][3] = f2tf32(af[(r + 8) * SSTR + kb + fc + 4]);
            } else {
                afr[mt][0] = as[r * SSTR + kb + fc];
                afr[mt][1] = as[(r + 8) * SSTR + kb + fc];
                afr[mt][2] = as[r * SSTR + kb + fc + 4];
                afr[mt][3] = as[(r + 8) * SSTR + kb + fc + 4];
            }
        }
        uint32_t bfr[4][2];
#pragma unroll
        for (int nt = 0; nt < 4; ++nt) {
            const int o = wn * 32 + nt * 8 + r8;
            bfr[nt][0] = bs[o * SSTR + kb + fc];
            bfr[nt][1] = bs[o * SSTR + kb + fc + 4];
        }
#pragma unroll
        for (int mt = 0; mt < 2; ++mt)
#pragma unroll
            for (int nt = 0; nt < 4; ++nt)
                mma_tf32(acc[mt][nt], afr[mt], bfr[nt]);
    }
}

// ch in [0,32): 0-15 = x/Wl, 16-31 = agg/Wr
__device__ __forceinline__ void gemm_issue_chunk(
    uint32_t smem_u32, int stage, int ch,
    const float* x, int rowBase, int colBase, int Nrows, int tid)
{
    const uint32_t sA = smem_u32 + (stage * STG_WORDS) * 4;
    const uint32_t sB = sA + A_WORDS * 4;
    const bool is_x = (ch < 16);
    const int kk = (ch & 15) * BK;
#pragma unroll
    for (int i = 0; i < 2; ++i) {                 // A: 64 x 32
        int idx = i * THREADS + tid;              // 0..511
        int r = idx >> 3, c4 = (idx & 7) * 4;
        int grow = rowBase + r;
        const void* g = is_x
            ? (const void*)(x + (size_t)grow * C_DIM + kk + c4)
            : (const void*)(g_agg + (size_t)grow * C_DIM + kk + c4);
        cp_async16(sA + (r * SSTR + c4) * 4, g, (grow < Nrows) ? 16 : 0);
    }
    const uint32_t* Bp = is_x ? g_wl : g_wr;
#pragma unroll
    for (int i = 0; i < 4; ++i) {                 // B: 128 x 32
        int idx = i * THREADS + tid;              // 0..1023
        int o = idx >> 3, c4 = (idx & 7) * 4;
        cp_async16(sB + (o * SSTR + c4) * 4,
                   Bp + (size_t)(colBase + o) * C_DIM + kk + c4, 16);
    }
    asm volatile("cp.async.commit_group;\n");
}

// ---------------------------------------------------------------------------
// Combo kernel: 16-bid groups = 14 mean pair-blocks + 2 full-K GEMM CTAs.
// ---------------------------------------------------------------------------
__global__ void __launch_bounds__(THREADS, 3)
combo_kernel(const float* __restrict__ x,
             const float* __restrict__ nx,
             const float* __restrict__ bl,
             const float* __restrict__ br,
             float* __restrict__ out,
             int Nrows)
{
    const int bid = blockIdx.x;
    const int g16 = bid >> 4;
    const int r   = bid & 15;
    const int tid = threadIdx.x;

    if (r >= 14) {
        // ==================== GEMM CTA (full K=1024) ====================
        const int gd = (g16 - GDELAY) * 2 + (r - 14);
        if (gd < 0 || gd >= GEMM_CTAS) return;

        extern __shared__ uint32_t smem[];
        const uint32_t smem_u32 = (uint32_t)__cvta_generic_to_shared(smem);
        const int lane = tid & 31;
        const int warp = tid >> 5;
        const int wm   = warp & 1;
        const int wn   = warp >> 1;
        const int rb      = gd >> 2;
        const int rowBase = rb * BM;
        const int colBase = (gd & 3) * BN;
        const int fc = lane & 3, r8 = lane >> 2;

        float acc[2][4][4];
#pragma unroll
        for (int mt = 0; mt < 2; ++mt)
#pragma unroll
            for (int nt = 0; nt < 4; ++nt)
#pragma unroll
                for (int i = 0; i < 4; ++i) acc[mt][nt][i] = 0.f;

        gemm_issue_chunk(smem_u32, 0, 0, x, rowBase, colBase, Nrows, tid);
        for (int t = 0; t < 32; ++t) {
            asm volatile("cp.async.wait_group 0;\n");
            __syncthreads();                      // chunk t visible; t-1 reads done
            if (t + 1 < 32) {
                if (t + 1 == 16) {
                    if (tid == 0) {
                        const int pairs  = (Nrows + 1) >> 1;
                        const int target = min(32, pairs - rb * 32);
                        int c;
                        do {
                            asm volatile("ld.acquire.gpu.global.s32 %0, [%1];"
                                         : "=r"(c) : "l"(g_cnt + rb) : "memory");
                        } while (c < target);
                    }
                    __syncthreads();
                }
                gemm_issue_chunk(smem_u32, (t + 1) & 1, t + 1,
                                 x, rowBase, colBase, Nrows, tid);
            }
            if (t < 16) gemm_compute_chunk<true >(smem + (t & 1) * STG_WORDS, acc, wm, wn, r8, fc);
            else        gemm_compute_chunk<false>(smem + (t & 1) * STG_WORDS, acc, wm, wn, r8, fc);
        }

        // epilogue: out = acc + (bl+br), streaming store
#pragma unroll
        for (int nt = 0; nt < 4; ++nt) {
            const int col = colBase + wn * 32 + nt * 8 + 2 * (lane & 3);
            const float b0 = __ldg(bl + col)     + __ldg(br + col);
            const float b1 = __ldg(bl + col + 1) + __ldg(br + col + 1);
#pragma unroll
            for (int mt = 0; mt < 2; ++mt) {
                const int row0 = rowBase + wm * 32 + mt * 16 + r8;
                const int row1 = row0 + 8;
                if (row0 < Nrows)
                    stg_cs(out + (size_t)row0 * OUT_DIM + col,
                           make_float2(acc[mt][nt][0] + b0, acc[mt][nt][1] + b1));
                if (row1 < Nrows)
                    stg_cs(out + (size_t)row1 * OUT_DIM + col,
                           make_float2(acc[mt][nt][2] + b0, acc[mt][nt][3] + b1));
            }
        }
    } else {
        // ==================== mean pair-block (2 nodes) ====================
        const int pair = g16 * 14 + r;
        if (pair * 2 >= Nrows) return;
        const int node = 2 * pair + (tid >> 7);
        const int c4   = tid & 127;
        if (node < Nrows) {
            const uint64_t pol = mk_evict_first_policy();
            const float4* p = reinterpret_cast<const float4*>(
                                  nx + (size_t)node * K_NB * C_DIM) + c4;
            float4 s[8];
#pragma unroll
            for (int j = 0; j < 8; ++j) s[j] = make_float4(0.f, 0.f, 0.f, 0.f);
#pragma unroll
            for (int k = 0; k < K_NB; k += 8) {   // 8 independent chains, deep MLP
                float4 v[8];
#pragma unroll
                for (int j = 0; j < 8; ++j)
                    v[j] = ldg_stream(p + (size_t)(k + j) * (C_DIM / 4), pol);
#pragma unroll
                for (int j = 0; j < 8; ++j) {
                    s[j].x += v[j].x; s[j].y += v[j].y;
                    s[j].z += v[j].z; s[j].w += v[j].w;
                }
            }
            const float inv = 1.0f / (float)K_NB;
            float4 t0, t1;
            t0.x = (s[0].x + s[1].x) + (s[2].x + s[3].x);
            t0.y = (s[0].y + s[1].y) + (s[2].y + s[3].y);
            t0.z = (s[0].z + s[1].z) + (s[2].z + s[3].z);
            t0.w = (s[0].w + s[1].w) + (s[2].w + s[3].w);
            t1.x = (s[4].x + s[5].x) + (s[6].x + s[7].x);
            t1.y = (s[4].y + s[5].y) + (s[6].y + s[7].y);
            t1.z = (s[4].z + s[5].z) + (s[6].z + s[7].z);
            t1.w = (s[4].w + s[5].w) + (s[6].w + s[7].w);
            uint4 o;
            o.x = f2tf32((t0.x + t1.x) * inv);
            o.y = f2tf32((t0.y + t1.y) * inv);
            o.z = f2tf32((t0.z + t1.z) * inv);
            o.w = f2tf32((t0.w + t1.w) * inv);
            reinterpret_cast<uint4*>(g_agg + (size_t)node * C_DIM)[c4] = o;
        }
        __syncthreads();                      // both nodes' stores complete
        if (tid == 0) {
            __threadfence();                  // publish g_agg before counting
            atomicAdd(g_cnt + (pair >> 5), 1);
        }
    }
}

// ---------------------------------------------------------------------------
// Launch
// ---------------------------------------------------------------------------
extern "C" void kernel_launch(void* const* d_in, const int* in_sizes, int n_in,
                              void* d_out, int out_size)
{
    const float* x     = (const float*)d_in[0];
    const float* neigh = (const float*)d_in[1];
    const float* Wl    = (const float*)d_in[2];
    const float* bl    = (const float*)d_in[3];
    const float* Wr    = (const float*)d_in[4];
    const float* br    = (const float*)d_in[5];
    float* out = (float*)d_out;

    const int N = in_sizes[0] / C_DIM;        // 20000

    wconv_kernel<<<512, 256>>>(Wl, Wr);       // also zeroes g_cnt

    static int smem_set = 0;
    if (!smem_set) {
        cudaFuncSetAttribute(combo_kernel, cudaFuncAttributeMaxDynamicSharedMemorySize, SMEM_BYTES);
        smem_set = 1;
    }

    const int pairs  = (N + 1) / 2;
    const int groups_mean = (pairs + 13) / 14;                 // 715
    const int groups_gemm = GEMM_CTAS / 2 + GDELAY;            // 642
    const int groups = (groups_mean > groups_gemm) ? groups_mean : groups_gemm;
    combo_kernel<<<groups * 16, THREADS, SMEM_BYTES>>>(x, neigh, bl, br, out, N);
}